// round 1
// baseline (speedup 1.0000x reference)
#include <cuda_runtime.h>

// Problem constants
#define BATCH 2
#define HFULL 128
#define WFULL 128
#define CCH   64
#define HLO   64
#define WLO   64
#define LQ    4096          // HLO*WLO
#define KC    576           // 3*3*CCH

static const size_t YSZ = (size_t)BATCH * HFULL * WFULL * CCH; // 2097152 floats (y output)

// -------- static device scratch (no allocation allowed) --------
__device__ float g_P[(size_t)BATCH * LQ * KC];     // normalized-source im2col of avgpooled image
__device__ float g_V[(size_t)BATCH * LQ * KC];     // raw full-res patches (stride-2 extraction)
__device__ float g_Z[(size_t)BATCH * LQ * KC];     // U @ V
__device__ float g_U[(size_t)BATCH * LQ * LQ];     // softmax attention (fused)
__device__ float g_invden[BATCH * LQ];             // 1 / max(||P_l||, 1e-4)
__device__ float g_mm[BATCH * LQ];                 // mask gate

// ===================================================================
// Kernel 1: build P (low-res im2col, SAME pad), V (raw patches), invden
// grid(LQ, BATCH), block 576
// ===================================================================
__global__ void __launch_bounds__(576) build_pv_kernel(const float* __restrict__ x)
{
    int b = blockIdx.y;
    int l = blockIdx.x;
    int li = l >> 6, lj = l & 63;
    int t = threadIdx.x;           // (dh*3+dw)*64 + c
    int c = t & 63;
    int g = t >> 6;
    int dh = g / 3, dw = g % 3;

    const size_t xb = (size_t)b * HFULL * WFULL * CCH;

    // P: avgpool2(x) patch at (li-1+dh, lj-1+dw), zero pad
    int fi = li - 1 + dh;
    int fj = lj - 1 + dw;
    float pv = 0.0f;
    if (fi >= 0 && fi < HLO && fj >= 0 && fj < WLO) {
        size_t base = xb + (size_t)(2 * fi) * (WFULL * CCH) + (size_t)(2 * fj) * CCH + c;
        pv = 0.25f * (x[base] + x[base + CCH] + x[base + WFULL * CCH] + x[base + WFULL * CCH + CCH]);
    }
    g_P[((size_t)b * LQ + l) * KC + t] = pv;

    // V: raw full-res patch at (2li+dh, 2lj+dw), zero pad at 128
    int xr = 2 * li + dh;
    int xc = 2 * lj + dw;
    float vv = 0.0f;
    if (xr < HFULL && xc < WFULL) {
        vv = x[xb + (size_t)xr * (WFULL * CCH) + (size_t)xc * CCH + c];
    }
    g_V[((size_t)b * LQ + l) * KC + t] = vv;

    // block reduce ||P_l||^2 over 576 threads
    __shared__ float s[576];
    s[t] = pv * pv;
    __syncthreads();
    if (t < 64) s[t] += s[t + 512];
    __syncthreads();
    for (int off = 256; off >= 1; off >>= 1) {
        if (t < off) s[t] += s[t + off];
        __syncthreads();
    }
    if (t == 0) {
        float nrm = sqrtf(s[0]);
        g_invden[b * LQ + l] = 1.0f / fmaxf(nrm, 1e-4f);
    }
}

// ===================================================================
// Kernel 2: mask gate mm[b,l] = (mean of 3x3 patch of avgpool2(mask) == 1)
// ===================================================================
__global__ void mm_kernel(const float* __restrict__ mask)
{
    int idx = blockIdx.x * blockDim.x + threadIdx.x;   // b*LQ + l
    if (idx >= BATCH * LQ) return;
    int b = idx / LQ;
    int l = idx % LQ;
    int li = l >> 6, lj = l & 63;
    const size_t mb = (size_t)b * HFULL * WFULL;

    float sum9 = 0.0f;
    for (int dh = 0; dh < 3; dh++) {
        for (int dw = 0; dw < 3; dw++) {
            int fi = li - 1 + dh, fj = lj - 1 + dw;
            if (fi >= 0 && fi < HLO && fj >= 0 && fj < WLO) {
                size_t base = mb + (size_t)(2 * fi) * WFULL + (2 * fj);
                sum9 += 0.25f * (mask[base] + mask[base + 1] + mask[base + WFULL] + mask[base + WFULL + 1]);
            }
        }
    }
    float mean = sum9 / 9.0f;
    g_mm[idx] = (mean == 1.0f) ? 1.0f : 0.0f;
}

// ===================================================================
// Kernel 3: score GEMM  att[b,p,q] = (P_p . P_q) * invden[q]
// C = A * A^T * diag(invden), M=N=4096, K=576
// 128x128 tile, BK=16, 256 threads, 8x8 per thread. Writes to d_out att region.
// ===================================================================
__global__ void __launch_bounds__(256) gemm_s_kernel(float* __restrict__ out)
{
    int b = blockIdx.z;
    const float* __restrict__ A = g_P + (size_t)b * LQ * KC;
    const float* __restrict__ inv = g_invden + b * LQ;
    float* __restrict__ Cb = out + YSZ + (size_t)b * LQ * LQ;

    int p0 = blockIdx.y * 128;
    int q0 = blockIdx.x * 128;

    __shared__ float Asm[16][128];
    __shared__ float Bsm[16][128];

    int t = threadIdx.x;
    int tx = t & 15, ty = t >> 4;

    float acc[8][8] = {};

    for (int kt = 0; kt < KC; kt += 16) {
#pragma unroll
        for (int r = 0; r < 2; r++) {
            int id = t + r * 256;          // 0..511
            int row = id >> 2, c4 = id & 3;
            float4 va = *(const float4*)(A + (size_t)(p0 + row) * KC + kt + c4 * 4);
            Asm[c4 * 4 + 0][row] = va.x;
            Asm[c4 * 4 + 1][row] = va.y;
            Asm[c4 * 4 + 2][row] = va.z;
            Asm[c4 * 4 + 3][row] = va.w;
            float4 vb = *(const float4*)(A + (size_t)(q0 + row) * KC + kt + c4 * 4);
            Bsm[c4 * 4 + 0][row] = vb.x;
            Bsm[c4 * 4 + 1][row] = vb.y;
            Bsm[c4 * 4 + 2][row] = vb.z;
            Bsm[c4 * 4 + 3][row] = vb.w;
        }
        __syncthreads();
#pragma unroll
        for (int k = 0; k < 16; k++) {
            float a[8], bb[8];
            *(float4*)(a)     = *(const float4*)&Asm[k][ty * 8];
            *(float4*)(a + 4) = *(const float4*)&Asm[k][ty * 8 + 4];
            *(float4*)(bb)     = *(const float4*)&Bsm[k][tx * 8];
            *(float4*)(bb + 4) = *(const float4*)&Bsm[k][tx * 8 + 4];
#pragma unroll
            for (int i = 0; i < 8; i++)
#pragma unroll
                for (int j = 0; j < 8; j++)
                    acc[i][j] += a[i] * bb[j];
        }
        __syncthreads();
    }

    float iv[8];
#pragma unroll
    for (int j = 0; j < 8; j++) iv[j] = inv[q0 + tx * 8 + j];
#pragma unroll
    for (int i = 0; i < 8; i++) {
        size_t off = (size_t)(p0 + ty * 8 + i) * LQ + q0 + tx * 8;
        float4 w0 = make_float4(acc[i][0] * iv[0], acc[i][1] * iv[1], acc[i][2] * iv[2], acc[i][3] * iv[3]);
        float4 w1 = make_float4(acc[i][4] * iv[4], acc[i][5] * iv[5], acc[i][6] * iv[6], acc[i][7] * iv[7]);
        *(float4*)(Cb + off)     = w0;
        *(float4*)(Cb + off + 4) = w1;
    }
}

// ===================================================================
// Kernel 4: fuse (two diagonal convs via 9-point gather) + stable softmax -> U
// grid(LQ, BATCH), block 256; each block = one attention row p
// ===================================================================
__global__ void __launch_bounds__(256) fuse_softmax_kernel(const float* __restrict__ out)
{
    int b = blockIdx.y;
    int p = blockIdx.x;
    const float* __restrict__ ab = out + YSZ + (size_t)b * LQ * LQ;
    const float* __restrict__ mmv = g_mm + b * LQ;
    float* __restrict__ Up = g_U + ((size_t)b * LQ + p) * LQ;

    int qi = p >> 6, qj = p & 63;
    int ap = (qj << 6) | qi;     // tau(p)

    __shared__ float zbuf[LQ];
    __shared__ float red[256];

    int t = threadIdx.x;
    float lmax = -3.4e38f;

    for (int ch = 0; ch < LQ / 256; ch++) {
        int l = t + ch * 256;
        int ki = l >> 6, kj = l & 63;
        int bp = (kj << 6) | ki; // tau(l)
        float acc = 0.0f;
#pragma unroll
        for (int d2 = -1; d2 <= 1; d2++) {
            int aa = ap + d2;
            int bb = bp + d2;
            if ((unsigned)aa < LQ && (unsigned)bb < LQ) {
                int u0 = ((aa & 63) << 6) | (aa >> 6);
                int v0 = ((bb & 63) << 6) | (bb >> 6);
#pragma unroll
                for (int d1 = -1; d1 <= 1; d1++) {
                    int uu = u0 + d1, vv = v0 + d1;
                    if ((unsigned)uu < LQ && (unsigned)vv < LQ)
                        acc += __ldg(ab + (size_t)uu * LQ + vv);
                }
            }
        }
        float z = acc * mmv[l] * 10.0f;   // masked -> exactly 0
        zbuf[l] = z;
        lmax = fmaxf(lmax, z);
    }

    // block max
    red[t] = lmax;
    __syncthreads();
    for (int off = 128; off >= 1; off >>= 1) {
        if (t < off) red[t] = fmaxf(red[t], red[t + off]);
        __syncthreads();
    }
    float rmax = red[0];
    __syncthreads();

    // exp + sum (sum includes masked entries, as in reference)
    float lsum = 0.0f;
    for (int ch = 0; ch < LQ / 256; ch++) {
        int l = t + ch * 256;
        float e = expf(zbuf[l] - rmax);
        zbuf[l] = e;
        lsum += e;
    }
    red[t] = lsum;
    __syncthreads();
    for (int off = 128; off >= 1; off >>= 1) {
        if (t < off) red[t] += red[t + off];
        __syncthreads();
    }
    float invs = 1.0f / red[0];
    __syncthreads();

    for (int ch = 0; ch < LQ / 256; ch++) {
        int l = t + ch * 256;
        Up[l] = zbuf[l] * invs * mmv[l];
    }
}

// ===================================================================
// Kernel 5: recon GEMM  Z[b,p,:] = sum_l U[b,p,l] * V[b,l,:]
// M=4096, N=576, K=4096; tile 128x64, BK=16, 256 threads, 8x4 per thread
// ===================================================================
__global__ void __launch_bounds__(256) gemm_z_kernel()
{
    int b = blockIdx.z;
    const float* __restrict__ A = g_U + (size_t)b * LQ * LQ;   // [4096,4096]
    const float* __restrict__ Bm = g_V + (size_t)b * LQ * KC;  // [4096,576]
    float* __restrict__ Cb = g_Z + (size_t)b * LQ * KC;

    int p0 = blockIdx.y * 128;
    int n0 = blockIdx.x * 64;

    __shared__ float Asm[16][128];
    __shared__ float Bsm[16][64];

    int t = threadIdx.x;
    int tx = t & 15, ty = t >> 4;

    float acc[8][4] = {};

    for (int kt = 0; kt < LQ; kt += 16) {
#pragma unroll
        for (int r = 0; r < 2; r++) {
            int id = t + r * 256;
            int row = id >> 2, c4 = id & 3;
            float4 va = *(const float4*)(A + (size_t)(p0 + row) * LQ + kt + c4 * 4);
            Asm[c4 * 4 + 0][row] = va.x;
            Asm[c4 * 4 + 1][row] = va.y;
            Asm[c4 * 4 + 2][row] = va.z;
            Asm[c4 * 4 + 3][row] = va.w;
        }
        {
            int row = t >> 4, c4 = t & 15;   // 16 rows x 16 float4
            float4 vb = *(const float4*)(Bm + (size_t)(kt + row) * KC + n0 + c4 * 4);
            Bsm[row][c4 * 4 + 0] = vb.x;
            Bsm[row][c4 * 4 + 1] = vb.y;
            Bsm[row][c4 * 4 + 2] = vb.z;
            Bsm[row][c4 * 4 + 3] = vb.w;
        }
        __syncthreads();
#pragma unroll
        for (int k = 0; k < 16; k++) {
            float a[8], bb[4];
            *(float4*)(a)     = *(const float4*)&Asm[k][ty * 8];
            *(float4*)(a + 4) = *(const float4*)&Asm[k][ty * 8 + 4];
            *(float4*)(bb)    = *(const float4*)&Bsm[k][tx * 4];
#pragma unroll
            for (int i = 0; i < 8; i++)
#pragma unroll
                for (int j = 0; j < 4; j++)
                    acc[i][j] += a[i] * bb[j];
        }
        __syncthreads();
    }

#pragma unroll
    for (int i = 0; i < 8; i++) {
        size_t off = (size_t)(p0 + ty * 8 + i) * KC + n0 + tx * 4;
        float4 w0 = make_float4(acc[i][0], acc[i][1], acc[i][2], acc[i][3]);
        *(float4*)(Cb + off) = w0;
    }
}

// ===================================================================
// Kernel 6: overlap-add (transposed conv gather), y = 0.25 * sum Z contributions
// ===================================================================
__global__ void recon_kernel(float* __restrict__ out)
{
    int idx = blockIdx.x * blockDim.x + threadIdx.x;  // ((b*128+I)*128+J)*64 + c
    if (idx >= (int)YSZ) return;
    int c = idx & 63;
    int tmp = idx >> 6;
    int J = tmp & 127; tmp >>= 7;
    int I = tmp & 127;
    int b = tmp >> 7;

    int ri[2], rdh[2], rn = 0;
    if (I & 1) { ri[0] = (I - 1) >> 1; rdh[0] = 1; rn = 1; }
    else {
        ri[rn] = I >> 1; rdh[rn] = 0; rn++;
        if (I >= 2) { ri[rn] = (I >> 1) - 1; rdh[rn] = 2; rn++; }
    }
    int cj[2], cdw[2], cn = 0;
    if (J & 1) { cj[0] = (J - 1) >> 1; cdw[0] = 1; cn = 1; }
    else {
        cj[cn] = J >> 1; cdw[cn] = 0; cn++;
        if (J >= 2) { cj[cn] = (J >> 1) - 1; cdw[cn] = 2; cn++; }
    }

    const float* __restrict__ Zb = g_Z + (size_t)b * LQ * KC;
    float acc = 0.0f;
    for (int a = 0; a < rn; a++) {
        for (int bb = 0; bb < cn; bb++) {
            int l = ri[a] * 64 + cj[bb];
            int n = (rdh[a] * 3 + cdw[bb]) * 64 + c;
            acc += Zb[(size_t)l * KC + n];
        }
    }
    out[idx] = 0.25f * acc;
}

// ===================================================================
extern "C" void kernel_launch(void* const* d_in, const int* in_sizes, int n_in,
                              void* d_out, int out_size)
{
    const float* x    = (const float*)d_in[0];
    const float* mask = (const float*)d_in[1];
    float* out = (float*)d_out;
    (void)in_sizes; (void)n_in; (void)out_size;

    build_pv_kernel<<<dim3(LQ, BATCH), 576>>>(x);
    mm_kernel<<<(BATCH * LQ + 255) / 256, 256>>>(mask);
    gemm_s_kernel<<<dim3(32, 32, BATCH), 256>>>(out);
    fuse_softmax_kernel<<<dim3(LQ, BATCH), 256>>>(out);
    gemm_z_kernel<<<dim3(KC / 64, 32, BATCH), 256>>>();
    recon_kernel<<<(int)((YSZ + 255) / 256), 256>>>(out);
}

// round 2
// speedup vs baseline: 1.0018x; 1.0018x over previous
#include <cuda_runtime.h>

// Problem constants
#define BATCH 2
#define HFULL 128
#define WFULL 128
#define CCH   64
#define HLO   64
#define WLO   64
#define LQ    4096          // HLO*WLO
#define KC    576           // 3*3*CCH

static const size_t YSZ = (size_t)BATCH * HFULL * WFULL * CCH; // 2097152 floats (y output)

// -------- static device scratch (no allocation allowed) --------
__device__ float g_P[(size_t)BATCH * LQ * KC];     // normalized-source im2col of avgpooled image
__device__ float g_V[(size_t)BATCH * LQ * KC];     // raw full-res patches (stride-2 extraction)
__device__ float g_Z[(size_t)BATCH * LQ * KC];     // U @ V
__device__ float g_U[(size_t)BATCH * LQ * LQ];     // softmax attention (fused)
__device__ float g_invden[BATCH * LQ];             // 1 / max(||P_l||, 1e-4)
__device__ float g_mm[BATCH * LQ];                 // mask gate

// ===================================================================
// Kernel 1: build P (low-res im2col, SAME pad), V (raw patches), invden
// grid(LQ, BATCH), block 576
// ===================================================================
__global__ void __launch_bounds__(576) build_pv_kernel(const float* __restrict__ x)
{
    int b = blockIdx.y;
    int l = blockIdx.x;
    int li = l >> 6, lj = l & 63;
    int t = threadIdx.x;           // (dh*3+dw)*64 + c
    int c = t & 63;
    int g = t >> 6;
    int dh = g / 3, dw = g % 3;

    const size_t xb = (size_t)b * HFULL * WFULL * CCH;

    // P: avgpool2(x) patch at (li-1+dh, lj-1+dw), zero pad
    int fi = li - 1 + dh;
    int fj = lj - 1 + dw;
    float pv = 0.0f;
    if (fi >= 0 && fi < HLO && fj >= 0 && fj < WLO) {
        size_t base = xb + (size_t)(2 * fi) * (WFULL * CCH) + (size_t)(2 * fj) * CCH + c;
        pv = 0.25f * (x[base] + x[base + CCH] + x[base + WFULL * CCH] + x[base + WFULL * CCH + CCH]);
    }
    g_P[((size_t)b * LQ + l) * KC + t] = pv;

    // V: raw full-res patch at (2li+dh, 2lj+dw), zero pad at 128
    int xr = 2 * li + dh;
    int xc = 2 * lj + dw;
    float vv = 0.0f;
    if (xr < HFULL && xc < WFULL) {
        vv = x[xb + (size_t)xr * (WFULL * CCH) + (size_t)xc * CCH + c];
    }
    g_V[((size_t)b * LQ + l) * KC + t] = vv;

    // block reduce ||P_l||^2 over 576 threads
    __shared__ float s[576];
    s[t] = pv * pv;
    __syncthreads();
    if (t < 64) s[t] += s[t + 512];
    __syncthreads();
    for (int off = 256; off >= 1; off >>= 1) {
        if (t < off) s[t] += s[t + off];
        __syncthreads();
    }
    if (t == 0) {
        float nrm = sqrtf(s[0]);
        g_invden[b * LQ + l] = 1.0f / fmaxf(nrm, 1e-4f);
    }
}

// ===================================================================
// Kernel 2: mask gate mm[b,l] = (mean of 3x3 patch of avgpool2(mask) == 1)
// ===================================================================
__global__ void mm_kernel(const float* __restrict__ mask)
{
    int idx = blockIdx.x * blockDim.x + threadIdx.x;   // b*LQ + l
    if (idx >= BATCH * LQ) return;
    int b = idx / LQ;
    int l = idx % LQ;
    int li = l >> 6, lj = l & 63;
    const size_t mb = (size_t)b * HFULL * WFULL;

    float sum9 = 0.0f;
    for (int dh = 0; dh < 3; dh++) {
        for (int dw = 0; dw < 3; dw++) {
            int fi = li - 1 + dh, fj = lj - 1 + dw;
            if (fi >= 0 && fi < HLO && fj >= 0 && fj < WLO) {
                size_t base = mb + (size_t)(2 * fi) * WFULL + (2 * fj);
                sum9 += 0.25f * (mask[base] + mask[base + 1] + mask[base + WFULL] + mask[base + WFULL + 1]);
            }
        }
    }
    float mean = sum9 / 9.0f;
    g_mm[idx] = (mean == 1.0f) ? 1.0f : 0.0f;
}

// ===================================================================
// Kernel 3: score GEMM  att[b,p,q] = (P_p . P_q) * invden[q]
// C = A * A^T * diag(invden), M=N=4096, K=576
// 128x128 tile, BK=16, 256 threads, 8x8 per thread. Writes to d_out att region.
// ===================================================================
__global__ void __launch_bounds__(256) gemm_s_kernel(float* __restrict__ out)
{
    int b = blockIdx.z;
    const float* __restrict__ A = g_P + (size_t)b * LQ * KC;
    const float* __restrict__ inv = g_invden + b * LQ;
    float* __restrict__ Cb = out + YSZ + (size_t)b * LQ * LQ;

    int p0 = blockIdx.y * 128;
    int q0 = blockIdx.x * 128;

    __shared__ float Asm[16][128];
    __shared__ float Bsm[16][128];

    int t = threadIdx.x;
    int tx = t & 15, ty = t >> 4;

    float acc[8][8] = {};

    for (int kt = 0; kt < KC; kt += 16) {
#pragma unroll
        for (int r = 0; r < 2; r++) {
            int id = t + r * 256;          // 0..511
            int row = id >> 2, c4 = id & 3;
            float4 va = *(const float4*)(A + (size_t)(p0 + row) * KC + kt + c4 * 4);
            Asm[c4 * 4 + 0][row] = va.x;
            Asm[c4 * 4 + 1][row] = va.y;
            Asm[c4 * 4 + 2][row] = va.z;
            Asm[c4 * 4 + 3][row] = va.w;
            float4 vb = *(const float4*)(A + (size_t)(q0 + row) * KC + kt + c4 * 4);
            Bsm[c4 * 4 + 0][row] = vb.x;
            Bsm[c4 * 4 + 1][row] = vb.y;
            Bsm[c4 * 4 + 2][row] = vb.z;
            Bsm[c4 * 4 + 3][row] = vb.w;
        }
        __syncthreads();
#pragma unroll
        for (int k = 0; k < 16; k++) {
            float a[8], bb[8];
            *(float4*)(a)     = *(const float4*)&Asm[k][ty * 8];
            *(float4*)(a + 4) = *(const float4*)&Asm[k][ty * 8 + 4];
            *(float4*)(bb)     = *(const float4*)&Bsm[k][tx * 8];
            *(float4*)(bb + 4) = *(const float4*)&Bsm[k][tx * 8 + 4];
#pragma unroll
            for (int i = 0; i < 8; i++)
#pragma unroll
                for (int j = 0; j < 8; j++)
                    acc[i][j] += a[i] * bb[j];
        }
        __syncthreads();
    }

    float iv[8];
#pragma unroll
    for (int j = 0; j < 8; j++) iv[j] = inv[q0 + tx * 8 + j];
#pragma unroll
    for (int i = 0; i < 8; i++) {
        size_t off = (size_t)(p0 + ty * 8 + i) * LQ + q0 + tx * 8;
        float4 w0 = make_float4(acc[i][0] * iv[0], acc[i][1] * iv[1], acc[i][2] * iv[2], acc[i][3] * iv[3]);
        float4 w1 = make_float4(acc[i][4] * iv[4], acc[i][5] * iv[5], acc[i][6] * iv[6], acc[i][7] * iv[7]);
        *(float4*)(Cb + off)     = w0;
        *(float4*)(Cb + off + 4) = w1;
    }
}

// ===================================================================
// Kernel 4: fuse (two diagonal convs via 9-point gather) + stable softmax -> U
// grid(LQ, BATCH), block 256; each block = one attention row p
// ===================================================================
__global__ void __launch_bounds__(256) fuse_softmax_kernel(const float* __restrict__ out)
{
    int b = blockIdx.y;
    int p = blockIdx.x;
    const float* __restrict__ ab = out + YSZ + (size_t)b * LQ * LQ;
    const float* __restrict__ mmv = g_mm + b * LQ;
    float* __restrict__ Up = g_U + ((size_t)b * LQ + p) * LQ;

    int qi = p >> 6, qj = p & 63;
    int ap = (qj << 6) | qi;     // tau(p)

    __shared__ float zbuf[LQ];
    __shared__ float red[256];

    int t = threadIdx.x;
    float lmax = -3.4e38f;

    for (int ch = 0; ch < LQ / 256; ch++) {
        int l = t + ch * 256;
        int ki = l >> 6, kj = l & 63;
        int bp = (kj << 6) | ki; // tau(l)
        float acc = 0.0f;
#pragma unroll
        for (int d2 = -1; d2 <= 1; d2++) {
            int aa = ap + d2;
            int bb = bp + d2;
            if ((unsigned)aa < LQ && (unsigned)bb < LQ) {
                int u0 = ((aa & 63) << 6) | (aa >> 6);
                int v0 = ((bb & 63) << 6) | (bb >> 6);
#pragma unroll
                for (int d1 = -1; d1 <= 1; d1++) {
                    int uu = u0 + d1, vv = v0 + d1;
                    if ((unsigned)uu < LQ && (unsigned)vv < LQ)
                        acc += __ldg(ab + (size_t)uu * LQ + vv);
                }
            }
        }
        float z = acc * mmv[l] * 10.0f;   // masked -> exactly 0
        zbuf[l] = z;
        lmax = fmaxf(lmax, z);
    }

    // block max
    red[t] = lmax;
    __syncthreads();
    for (int off = 128; off >= 1; off >>= 1) {
        if (t < off) red[t] = fmaxf(red[t], red[t + off]);
        __syncthreads();
    }
    float rmax = red[0];
    __syncthreads();

    // exp + sum (sum includes masked entries, as in reference)
    float lsum = 0.0f;
    for (int ch = 0; ch < LQ / 256; ch++) {
        int l = t + ch * 256;
        float e = expf(zbuf[l] - rmax);
        zbuf[l] = e;
        lsum += e;
    }
    red[t] = lsum;
    __syncthreads();
    for (int off = 128; off >= 1; off >>= 1) {
        if (t < off) red[t] += red[t + off];
        __syncthreads();
    }
    float invs = 1.0f / red[0];
    __syncthreads();

    for (int ch = 0; ch < LQ / 256; ch++) {
        int l = t + ch * 256;
        Up[l] = zbuf[l] * invs * mmv[l];
    }
}

// ===================================================================
// Kernel 5: recon GEMM  Z[b,p,:] = sum_l U[b,p,l] * V[b,l,:]
// M=4096, N=576, K=4096; tile 128x64, BK=16, 256 threads, 8x4 per thread
// ===================================================================
__global__ void __launch_bounds__(256) gemm_z_kernel()
{
    int b = blockIdx.z;
    const float* __restrict__ A = g_U + (size_t)b * LQ * LQ;   // [4096,4096]
    const float* __restrict__ Bm = g_V + (size_t)b * LQ * KC;  // [4096,576]
    float* __restrict__ Cb = g_Z + (size_t)b * LQ * KC;

    int p0 = blockIdx.y * 128;
    int n0 = blockIdx.x * 64;

    __shared__ float Asm[16][128];
    __shared__ float Bsm[16][64];

    int t = threadIdx.x;
    int tx = t & 15, ty = t >> 4;

    float acc[8][4] = {};

    for (int kt = 0; kt < LQ; kt += 16) {
#pragma unroll
        for (int r = 0; r < 2; r++) {
            int id = t + r * 256;
            int row = id >> 2, c4 = id & 3;
            float4 va = *(const float4*)(A + (size_t)(p0 + row) * LQ + kt + c4 * 4);
            Asm[c4 * 4 + 0][row] = va.x;
            Asm[c4 * 4 + 1][row] = va.y;
            Asm[c4 * 4 + 2][row] = va.z;
            Asm[c4 * 4 + 3][row] = va.w;
        }
        {
            int row = t >> 4, c4 = t & 15;   // 16 rows x 16 float4
            float4 vb = *(const float4*)(Bm + (size_t)(kt + row) * KC + n0 + c4 * 4);
            Bsm[row][c4 * 4 + 0] = vb.x;
            Bsm[row][c4 * 4 + 1] = vb.y;
            Bsm[row][c4 * 4 + 2] = vb.z;
            Bsm[row][c4 * 4 + 3] = vb.w;
        }
        __syncthreads();
#pragma unroll
        for (int k = 0; k < 16; k++) {
            float a[8], bb[4];
            *(float4*)(a)     = *(const float4*)&Asm[k][ty * 8];
            *(float4*)(a + 4) = *(const float4*)&Asm[k][ty * 8 + 4];
            *(float4*)(bb)    = *(const float4*)&Bsm[k][tx * 4];
#pragma unroll
            for (int i = 0; i < 8; i++)
#pragma unroll
                for (int j = 0; j < 4; j++)
                    acc[i][j] += a[i] * bb[j];
        }
        __syncthreads();
    }

#pragma unroll
    for (int i = 0; i < 8; i++) {
        size_t off = (size_t)(p0 + ty * 8 + i) * KC + n0 + tx * 4;
        float4 w0 = make_float4(acc[i][0], acc[i][1], acc[i][2], acc[i][3]);
        *(float4*)(Cb + off) = w0;
    }
}

// ===================================================================
// Kernel 6: overlap-add (transposed conv gather), y = 0.25 * sum Z contributions
// ===================================================================
__global__ void recon_kernel(float* __restrict__ out)
{
    int idx = blockIdx.x * blockDim.x + threadIdx.x;  // ((b*128+I)*128+J)*64 + c
    if (idx >= (int)YSZ) return;
    int c = idx & 63;
    int tmp = idx >> 6;
    int J = tmp & 127; tmp >>= 7;
    int I = tmp & 127;
    int b = tmp >> 7;

    int ri[2], rdh[2], rn = 0;
    if (I & 1) { ri[0] = (I - 1) >> 1; rdh[0] = 1; rn = 1; }
    else {
        ri[rn] = I >> 1; rdh[rn] = 0; rn++;
        if (I >= 2) { ri[rn] = (I >> 1) - 1; rdh[rn] = 2; rn++; }
    }
    int cj[2], cdw[2], cn = 0;
    if (J & 1) { cj[0] = (J - 1) >> 1; cdw[0] = 1; cn = 1; }
    else {
        cj[cn] = J >> 1; cdw[cn] = 0; cn++;
        if (J >= 2) { cj[cn] = (J >> 1) - 1; cdw[cn] = 2; cn++; }
    }

    const float* __restrict__ Zb = g_Z + (size_t)b * LQ * KC;
    float acc = 0.0f;
    for (int a = 0; a < rn; a++) {
        for (int bb = 0; bb < cn; bb++) {
            int l = ri[a] * 64 + cj[bb];
            int n = (rdh[a] * 3 + cdw[bb]) * 64 + c;
            acc += Zb[(size_t)l * KC + n];
        }
    }
    out[idx] = 0.25f * acc;
}

// ===================================================================
extern "C" void kernel_launch(void* const* d_in, const int* in_sizes, int n_in,
                              void* d_out, int out_size)
{
    const float* x    = (const float*)d_in[0];
    const float* mask = (const float*)d_in[1];
    float* out = (float*)d_out;
    (void)in_sizes; (void)n_in; (void)out_size;

    build_pv_kernel<<<dim3(LQ, BATCH), 576>>>(x);
    mm_kernel<<<(BATCH * LQ + 255) / 256, 256>>>(mask);
    gemm_s_kernel<<<dim3(32, 32, BATCH), 256>>>(out);
    fuse_softmax_kernel<<<dim3(LQ, BATCH), 256>>>(out);
    gemm_z_kernel<<<dim3(KC / 64, 32, BATCH), 256>>>();
    recon_kernel<<<(int)((YSZ + 255) / 256), 256>>>(out);
}

// round 3
// speedup vs baseline: 2.3619x; 2.3577x over previous
#include <cuda_runtime.h>

// Problem constants
#define BATCH 2
#define HFULL 128
#define WFULL 128
#define CCH   64
#define HLO   64
#define WLO   64
#define LQ    4096          // HLO*WLO
#define KC    576           // 3*3*CCH

static const size_t YSZ = (size_t)BATCH * HFULL * WFULL * CCH; // 2097152 floats (y output)

// -------- static device scratch (no allocation allowed) --------
__device__ float g_P[(size_t)BATCH * LQ * KC];     // im2col of avgpooled image
__device__ float g_V[(size_t)BATCH * LQ * KC];     // raw full-res patches (stride-2 extraction)
__device__ float g_Vc[(size_t)BATCH * LQ * KC];    // compacted V rows (active columns only)
__device__ float g_Z[(size_t)BATCH * LQ * KC];     // U @ V
__device__ float g_U[(size_t)BATCH * LQ * LQ];     // softmax attention, COMPACTED columns
__device__ float g_invden[BATCH * LQ];             // 1 / max(||P_l||, 1e-4)
__device__ float g_mm[BATCH * LQ];                 // mask gate
__device__ int   g_idx[BATCH * LQ];                // active column index list
__device__ int   g_cnt[BATCH * 2];                 // {count, countPad16} per batch

// ===================================================================
// Kernel 1: build P (low-res im2col, SAME pad), V (raw patches), invden
// ===================================================================
__global__ void __launch_bounds__(576) build_pv_kernel(const float* __restrict__ x)
{
    int b = blockIdx.y;
    int l = blockIdx.x;
    int li = l >> 6, lj = l & 63;
    int t = threadIdx.x;           // (dh*3+dw)*64 + c
    int c = t & 63;
    int g = t >> 6;
    int dh = g / 3, dw = g % 3;

    const size_t xb = (size_t)b * HFULL * WFULL * CCH;

    int fi = li - 1 + dh;
    int fj = lj - 1 + dw;
    float pv = 0.0f;
    if (fi >= 0 && fi < HLO && fj >= 0 && fj < WLO) {
        size_t base = xb + (size_t)(2 * fi) * (WFULL * CCH) + (size_t)(2 * fj) * CCH + c;
        pv = 0.25f * (x[base] + x[base + CCH] + x[base + WFULL * CCH] + x[base + WFULL * CCH + CCH]);
    }
    g_P[((size_t)b * LQ + l) * KC + t] = pv;

    int xr = 2 * li + dh;
    int xc = 2 * lj + dw;
    float vv = 0.0f;
    if (xr < HFULL && xc < WFULL) {
        vv = x[xb + (size_t)xr * (WFULL * CCH) + (size_t)xc * CCH + c];
    }
    g_V[((size_t)b * LQ + l) * KC + t] = vv;

    __shared__ float s[576];
    s[t] = pv * pv;
    __syncthreads();
    if (t < 64) s[t] += s[t + 512];
    __syncthreads();
    for (int off = 256; off >= 1; off >>= 1) {
        if (t < off) s[t] += s[t + off];
        __syncthreads();
    }
    if (t == 0) {
        float nrm = sqrtf(s[0]);
        g_invden[b * LQ + l] = 1.0f / fmaxf(nrm, 1e-4f);
    }
}

// ===================================================================
// Kernel 2: mask gate
// ===================================================================
__global__ void mm_kernel(const float* __restrict__ mask)
{
    int idx = blockIdx.x * blockDim.x + threadIdx.x;
    if (idx >= BATCH * LQ) return;
    int b = idx / LQ;
    int l = idx % LQ;
    int li = l >> 6, lj = l & 63;
    const size_t mb = (size_t)b * HFULL * WFULL;

    float sum9 = 0.0f;
    for (int dh = 0; dh < 3; dh++) {
        for (int dw = 0; dw < 3; dw++) {
            int fi = li - 1 + dh, fj = lj - 1 + dw;
            if (fi >= 0 && fi < HLO && fj >= 0 && fj < WLO) {
                size_t base = mb + (size_t)(2 * fi) * WFULL + (2 * fj);
                sum9 += 0.25f * (mask[base] + mask[base + 1] + mask[base + WFULL] + mask[base + WFULL + 1]);
            }
        }
    }
    float mean = sum9 / 9.0f;
    g_mm[idx] = (mean == 1.0f) ? 1.0f : 0.0f;
}

// ===================================================================
// Kernel 2b: deterministic compaction of active columns (block scan)
// grid BATCH, block 1024; each thread handles 4 consecutive l
// ===================================================================
__global__ void __launch_bounds__(1024) compact_kernel()
{
    int b = blockIdx.x;
    int t = threadIdx.x;
    __shared__ int sc[1024];

    int base = t * 4;
    int loc[4];
    int cnt = 0;
#pragma unroll
    for (int i = 0; i < 4; i++) {
        loc[i] = (g_mm[b * LQ + base + i] != 0.0f) ? 1 : 0;
        cnt += loc[i];
    }
    sc[t] = cnt;
    __syncthreads();
    // Hillis-Steele inclusive scan
    for (int off = 1; off < 1024; off <<= 1) {
        int v = (t >= off) ? sc[t - off] : 0;
        __syncthreads();
        sc[t] += v;
        __syncthreads();
    }
    int pos = sc[t] - cnt;   // exclusive prefix
#pragma unroll
    for (int i = 0; i < 4; i++) {
        if (loc[i]) g_idx[b * LQ + (pos++)] = base + i;
    }
    if (t == 1023) {
        int total = sc[1023];
        int pad = (total + 15) & ~15;
        g_cnt[b * 2 + 0] = total;
        g_cnt[b * 2 + 1] = pad;
        for (int j = total; j < pad; j++) g_idx[b * LQ + j] = 0;
    }
}

// ===================================================================
// Kernel 2c: gather compacted V rows (zero padding rows)
// grid (LQ, BATCH), block 576
// ===================================================================
__global__ void __launch_bounds__(576) vcomp_kernel()
{
    int b = blockIdx.y;
    int j = blockIdx.x;
    int cnt = g_cnt[b * 2 + 0];
    int pad = g_cnt[b * 2 + 1];
    if (j >= pad) return;
    int t = threadIdx.x;
    float v = 0.0f;
    if (j < cnt) {
        int l = g_idx[b * LQ + j];
        v = g_V[((size_t)b * LQ + l) * KC + t];
    }
    g_Vc[((size_t)b * LQ + j) * KC + t] = v;
}

// ===================================================================
// Kernel 3: score GEMM  att[b,p,q] = (P_p . P_q) * invden[q]
// Symmetric: compute only block-upper-triangle (qb >= pb), write both halves.
// ===================================================================
__global__ void __launch_bounds__(256) gemm_s_kernel(float* __restrict__ out)
{
    if (blockIdx.x < blockIdx.y) return;   // lower block-triangle: skip

    int b = blockIdx.z;
    const float* __restrict__ A = g_P + (size_t)b * LQ * KC;
    const float* __restrict__ inv = g_invden + b * LQ;
    float* __restrict__ Cb = out + YSZ + (size_t)b * LQ * LQ;

    int p0 = blockIdx.y * 128;
    int q0 = blockIdx.x * 128;

    __shared__ float Asm[16][128];
    __shared__ float Bsm[16][128];

    int t = threadIdx.x;
    int tx = t & 15, ty = t >> 4;

    float acc[8][8] = {};

    for (int kt = 0; kt < KC; kt += 16) {
#pragma unroll
        for (int r = 0; r < 2; r++) {
            int id = t + r * 256;
            int row = id >> 2, c4 = id & 3;
            float4 va = *(const float4*)(A + (size_t)(p0 + row) * KC + kt + c4 * 4);
            Asm[c4 * 4 + 0][row] = va.x;
            Asm[c4 * 4 + 1][row] = va.y;
            Asm[c4 * 4 + 2][row] = va.z;
            Asm[c4 * 4 + 3][row] = va.w;
            float4 vb = *(const float4*)(A + (size_t)(q0 + row) * KC + kt + c4 * 4);
            Bsm[c4 * 4 + 0][row] = vb.x;
            Bsm[c4 * 4 + 1][row] = vb.y;
            Bsm[c4 * 4 + 2][row] = vb.z;
            Bsm[c4 * 4 + 3][row] = vb.w;
        }
        __syncthreads();
#pragma unroll
        for (int k = 0; k < 16; k++) {
            float a[8], bb[8];
            *(float4*)(a)     = *(const float4*)&Asm[k][ty * 8];
            *(float4*)(a + 4) = *(const float4*)&Asm[k][ty * 8 + 4];
            *(float4*)(bb)     = *(const float4*)&Bsm[k][tx * 8];
            *(float4*)(bb + 4) = *(const float4*)&Bsm[k][tx * 8 + 4];
#pragma unroll
            for (int i = 0; i < 8; i++)
#pragma unroll
                for (int j = 0; j < 8; j++)
                    acc[i][j] += a[i] * bb[j];
        }
        __syncthreads();
    }

    // normal half: C[p][q] = dot * inv[q]
    float iv[8];
#pragma unroll
    for (int j = 0; j < 8; j++) iv[j] = inv[q0 + tx * 8 + j];
#pragma unroll
    for (int i = 0; i < 8; i++) {
        size_t off = (size_t)(p0 + ty * 8 + i) * LQ + q0 + tx * 8;
        float4 w0 = make_float4(acc[i][0] * iv[0], acc[i][1] * iv[1], acc[i][2] * iv[2], acc[i][3] * iv[3]);
        float4 w1 = make_float4(acc[i][4] * iv[4], acc[i][5] * iv[5], acc[i][6] * iv[6], acc[i][7] * iv[7]);
        *(float4*)(Cb + off)     = w0;
        *(float4*)(Cb + off + 4) = w1;
    }

    // mirrored half: C[q][p] = dot * inv[p]  (diagonal tiles re-write identical values)
    float ivp[8];
#pragma unroll
    for (int i = 0; i < 8; i++) ivp[i] = inv[p0 + ty * 8 + i];
#pragma unroll
    for (int j = 0; j < 8; j++) {
        size_t offT = (size_t)(q0 + tx * 8 + j) * LQ + p0 + ty * 8;
        float4 u0 = make_float4(acc[0][j] * ivp[0], acc[1][j] * ivp[1], acc[2][j] * ivp[2], acc[3][j] * ivp[3]);
        float4 u1 = make_float4(acc[4][j] * ivp[4], acc[5][j] * ivp[5], acc[6][j] * ivp[6], acc[7][j] * ivp[7]);
        *(float4*)(Cb + offT)     = u0;
        *(float4*)(Cb + offT + 4) = u1;
    }
}

// ===================================================================
// Kernel 4: fuse + stable softmax, ACTIVE COLUMNS ONLY -> compacted U
// masked logits are exactly 0: max folds in 0, denom adds (LQ-count)*exp(-max)
// ===================================================================
__global__ void __launch_bounds__(256) fuse_softmax_kernel(const float* __restrict__ out)
{
    int b = blockIdx.y;
    int p = blockIdx.x;
    const float* __restrict__ ab = out + YSZ + (size_t)b * LQ * LQ;
    const int* __restrict__ idxb = g_idx + b * LQ;
    float* __restrict__ Up = g_U + ((size_t)b * LQ + p) * LQ;

    int cnt = g_cnt[b * 2 + 0];
    int pad = g_cnt[b * 2 + 1];

    int qi = p >> 6, qj = p & 63;
    int ap = (qj << 6) | qi;     // tau(p)

    __shared__ float zbuf[LQ];
    __shared__ float red[256];

    int t = threadIdx.x;
    float lmax = (cnt < LQ) ? 0.0f : -3.4e38f;   // masked entries contribute logit 0

    for (int j = t; j < pad; j += 256) {
        float z = 0.0f;
        if (j < cnt) {
            int l = __ldg(idxb + j);
            int ki = l >> 6, kj = l & 63;
            int bp = (kj << 6) | ki;   // tau(l)
            float acc = 0.0f;
#pragma unroll
            for (int d2 = -1; d2 <= 1; d2++) {
                int aa = ap + d2;
                int bb = bp + d2;
                if ((unsigned)aa < LQ && (unsigned)bb < LQ) {
                    int u0 = ((aa & 63) << 6) | (aa >> 6);
                    int v0 = ((bb & 63) << 6) | (bb >> 6);
#pragma unroll
                    for (int d1 = -1; d1 <= 1; d1++) {
                        int uu = u0 + d1, vv = v0 + d1;
                        if ((unsigned)uu < LQ && (unsigned)vv < LQ)
                            acc += __ldg(ab + (size_t)uu * LQ + vv);
                    }
                }
            }
            z = acc * 10.0f;   // mm==1 for active columns
            lmax = fmaxf(lmax, z);
        }
        zbuf[j] = z;
    }

    red[t] = lmax;
    __syncthreads();
    for (int off = 128; off >= 1; off >>= 1) {
        if (t < off) red[t] = fmaxf(red[t], red[t + off]);
        __syncthreads();
    }
    float rmax = red[0];
    __syncthreads();

    float lsum = 0.0f;
    for (int j = t; j < pad; j += 256) {
        float e = 0.0f;
        if (j < cnt) {
            e = expf(zbuf[j] - rmax);
            lsum += e;
        }
        zbuf[j] = e;
    }
    red[t] = lsum;
    __syncthreads();
    for (int off = 128; off >= 1; off >>= 1) {
        if (t < off) red[t] += red[t + off];
        __syncthreads();
    }
    float den = red[0] + (float)(LQ - cnt) * expf(-rmax);
    float invs = 1.0f / den;
    __syncthreads();

    for (int j = t; j < pad; j += 256) {
        Up[j] = zbuf[j] * invs;   // padding slots hold 0
    }
}

// ===================================================================
// Kernel 5: recon GEMM  Z[b,p,:] = sum_{j<pad} Ucomp[b,p,j] * Vcomp[b,j,:]
// K bound read from device (compacted active count, padded to 16)
// ===================================================================
__global__ void __launch_bounds__(256) gemm_z_kernel()
{
    int b = blockIdx.z;
    const float* __restrict__ A = g_U + (size_t)b * LQ * LQ;    // [4096, pad] (stride LQ)
    const float* __restrict__ Bm = g_Vc + (size_t)b * LQ * KC;  // [pad, 576]
    float* __restrict__ Cb = g_Z + (size_t)b * LQ * KC;

    int kmax = g_cnt[b * 2 + 1];

    int p0 = blockIdx.y * 128;
    int n0 = blockIdx.x * 64;

    __shared__ float Asm[16][128];
    __shared__ float Bsm[16][64];

    int t = threadIdx.x;
    int tx = t & 15, ty = t >> 4;

    float acc[8][4] = {};

    for (int kt = 0; kt < kmax; kt += 16) {
#pragma unroll
        for (int r = 0; r < 2; r++) {
            int id = t + r * 256;
            int row = id >> 2, c4 = id & 3;
            float4 va = *(const float4*)(A + (size_t)(p0 + row) * LQ + kt + c4 * 4);
            Asm[c4 * 4 + 0][row] = va.x;
            Asm[c4 * 4 + 1][row] = va.y;
            Asm[c4 * 4 + 2][row] = va.z;
            Asm[c4 * 4 + 3][row] = va.w;
        }
        {
            int row = t >> 4, c4 = t & 15;
            float4 vb = *(const float4*)(Bm + (size_t)(kt + row) * KC + n0 + c4 * 4);
            Bsm[row][c4 * 4 + 0] = vb.x;
            Bsm[row][c4 * 4 + 1] = vb.y;
            Bsm[row][c4 * 4 + 2] = vb.z;
            Bsm[row][c4 * 4 + 3] = vb.w;
        }
        __syncthreads();
#pragma unroll
        for (int k = 0; k < 16; k++) {
            float a[8], bb[4];
            *(float4*)(a)     = *(const float4*)&Asm[k][ty * 8];
            *(float4*)(a + 4) = *(const float4*)&Asm[k][ty * 8 + 4];
            *(float4*)(bb)    = *(const float4*)&Bsm[k][tx * 4];
#pragma unroll
            for (int i = 0; i < 8; i++)
#pragma unroll
                for (int j = 0; j < 4; j++)
                    acc[i][j] += a[i] * bb[j];
        }
        __syncthreads();
    }

#pragma unroll
    for (int i = 0; i < 8; i++) {
        size_t off = (size_t)(p0 + ty * 8 + i) * KC + n0 + tx * 4;
        float4 w0 = make_float4(acc[i][0], acc[i][1], acc[i][2], acc[i][3]);
        *(float4*)(Cb + off) = w0;
    }
}

// ===================================================================
// Kernel 6: overlap-add (transposed conv gather)
// ===================================================================
__global__ void recon_kernel(float* __restrict__ out)
{
    int idx = blockIdx.x * blockDim.x + threadIdx.x;
    if (idx >= (int)YSZ) return;
    int c = idx & 63;
    int tmp = idx >> 6;
    int J = tmp & 127; tmp >>= 7;
    int I = tmp & 127;
    int b = tmp >> 7;

    int ri[2], rdh[2], rn = 0;
    if (I & 1) { ri[0] = (I - 1) >> 1; rdh[0] = 1; rn = 1; }
    else {
        ri[rn] = I >> 1; rdh[rn] = 0; rn++;
        if (I >= 2) { ri[rn] = (I >> 1) - 1; rdh[rn] = 2; rn++; }
    }
    int cj[2], cdw[2], cn = 0;
    if (J & 1) { cj[0] = (J - 1) >> 1; cdw[0] = 1; cn = 1; }
    else {
        cj[cn] = J >> 1; cdw[cn] = 0; cn++;
        if (J >= 2) { cj[cn] = (J >> 1) - 1; cdw[cn] = 2; cn++; }
    }

    const float* __restrict__ Zb = g_Z + (size_t)b * LQ * KC;
    float acc = 0.0f;
    for (int a = 0; a < rn; a++) {
        for (int bb = 0; bb < cn; bb++) {
            int l = ri[a] * 64 + cj[bb];
            int n = (rdh[a] * 3 + cdw[bb]) * 64 + c;
            acc += Zb[(size_t)l * KC + n];
        }
    }
    out[idx] = 0.25f * acc;
}

// ===================================================================
extern "C" void kernel_launch(void* const* d_in, const int* in_sizes, int n_in,
                              void* d_out, int out_size)
{
    const float* x    = (const float*)d_in[0];
    const float* mask = (const float*)d_in[1];
    float* out = (float*)d_out;
    (void)in_sizes; (void)n_in; (void)out_size;

    build_pv_kernel<<<dim3(LQ, BATCH), 576>>>(x);
    mm_kernel<<<(BATCH * LQ + 255) / 256, 256>>>(mask);
    compact_kernel<<<BATCH, 1024>>>();
    vcomp_kernel<<<dim3(LQ, BATCH), 576>>>();
    gemm_s_kernel<<<dim3(32, 32, BATCH), 256>>>(out);
    fuse_softmax_kernel<<<dim3(LQ, BATCH), 256>>>(out);
    gemm_z_kernel<<<dim3(KC / 64, 32, BATCH), 256>>>();
    recon_kernel<<<(int)((YSZ + 255) / 256), 256>>>(out);
}

// round 5
// speedup vs baseline: 2.9767x; 1.2603x over previous
#include <cuda_runtime.h>
#include <cuda_bf16.h>
#include <cstdint>

// Problem constants
#define BATCH 2
#define HFULL 128
#define WFULL 128
#define CCH   64
#define HLO   64
#define WLO   64
#define LQ    4096          // HLO*WLO
#define KC    576           // 3*3*CCH
#define KP    1152          // split width: [hi(576) | lo(576)]

static const size_t YSZ = (size_t)BATCH * HFULL * WFULL * CCH; // y output floats

// -------- static device scratch --------
__device__ __align__(16) __nv_bfloat16 g_Pbf[(size_t)BATCH * LQ * KP];  // [hi|lo] per row
__device__ float g_V[(size_t)BATCH * LQ * KC];
__device__ float g_Vc[(size_t)BATCH * LQ * KC];
__device__ float g_Z[(size_t)BATCH * LQ * KC];
__device__ float g_U[(size_t)BATCH * LQ * LQ];
__device__ float g_invden[BATCH * LQ];
__device__ float g_mm[BATCH * LQ];
__device__ int   g_idx[BATCH * LQ];
__device__ int   g_cnt[BATCH * 2];

// ---------------- helpers (all baseline sm_80-era PTX, safe on compute_103) ----
__device__ __forceinline__ uint32_t smem_u32(const void* p) {
    uint32_t a;
    asm("{ .reg .u64 t; cvta.to.shared.u64 t, %1; cvt.u32.u64 %0, t; }" : "=r"(a) : "l"(p));
    return a;
}
__device__ __forceinline__ void cp16(uint32_t dst, const void* src) {
    asm volatile("cp.async.cg.shared.global [%0], [%1], 16;" :: "r"(dst), "l"(src));
}
__device__ __forceinline__ void cp_commit() {
    asm volatile("cp.async.commit_group;");
}
template<int N> __device__ __forceinline__ void cp_wait() {
    asm volatile("cp.async.wait_group %0;" :: "n"(N));
}
__device__ __forceinline__ void ldsm4(uint32_t a, uint32_t& r0, uint32_t& r1, uint32_t& r2, uint32_t& r3) {
    asm volatile("ldmatrix.sync.aligned.m8n8.x4.shared.b16 {%0,%1,%2,%3}, [%4];"
                 : "=r"(r0), "=r"(r1), "=r"(r2), "=r"(r3) : "r"(a));
}
__device__ __forceinline__ void mma16816(float& c0, float& c1, float& c2, float& c3,
                                         uint32_t a0, uint32_t a1, uint32_t a2, uint32_t a3,
                                         uint32_t b0, uint32_t b1) {
    asm volatile("mma.sync.aligned.m16n8k16.row.col.f32.bf16.bf16.f32 "
                 "{%0,%1,%2,%3}, {%4,%5,%6,%7}, {%8,%9}, {%0,%1,%2,%3};"
                 : "+f"(c0), "+f"(c1), "+f"(c2), "+f"(c3)
                 : "r"(a0), "r"(a1), "r"(a2), "r"(a3), "r"(b0), "r"(b1));
}

// ===================================================================
// Kernel 1: build split-bf16 P, V (raw patches), invden
// ===================================================================
__global__ void __launch_bounds__(576) build_pv_kernel(const float* __restrict__ x)
{
    int b = blockIdx.y;
    int l = blockIdx.x;
    int li = l >> 6, lj = l & 63;
    int t = threadIdx.x;
    int c = t & 63;
    int g = t >> 6;
    int dh = g / 3, dw = g % 3;

    const size_t xb = (size_t)b * HFULL * WFULL * CCH;

    int fi = li - 1 + dh;
    int fj = lj - 1 + dw;
    float pv = 0.0f;
    if (fi >= 0 && fi < HLO && fj >= 0 && fj < WLO) {
        size_t base = xb + (size_t)(2 * fi) * (WFULL * CCH) + (size_t)(2 * fj) * CCH + c;
        pv = 0.25f * (x[base] + x[base + CCH] + x[base + WFULL * CCH] + x[base + WFULL * CCH + CCH]);
    }
    __nv_bfloat16 hi = __float2bfloat16(pv);
    float lof = pv - __bfloat162float(hi);
    __nv_bfloat16 lo = __float2bfloat16(lof);
    size_t rb = ((size_t)b * LQ + l) * KP;
    g_Pbf[rb + t] = hi;
    g_Pbf[rb + KC + t] = lo;

    int xr = 2 * li + dh;
    int xc = 2 * lj + dw;
    float vv = 0.0f;
    if (xr < HFULL && xc < WFULL) {
        vv = x[xb + (size_t)xr * (WFULL * CCH) + (size_t)xc * CCH + c];
    }
    g_V[((size_t)b * LQ + l) * KC + t] = vv;

    __shared__ float s[576];
    s[t] = pv * pv;
    __syncthreads();
    if (t < 64) s[t] += s[t + 512];
    __syncthreads();
    for (int off = 256; off >= 1; off >>= 1) {
        if (t < off) s[t] += s[t + off];
        __syncthreads();
    }
    if (t == 0) {
        float nrm = sqrtf(s[0]);
        g_invden[b * LQ + l] = 1.0f / fmaxf(nrm, 1e-4f);
    }
}

// ===================================================================
// Kernel 2: mask gate
// ===================================================================
__global__ void mm_kernel(const float* __restrict__ mask)
{
    int idx = blockIdx.x * blockDim.x + threadIdx.x;
    if (idx >= BATCH * LQ) return;
    int b = idx / LQ;
    int l = idx % LQ;
    int li = l >> 6, lj = l & 63;
    const size_t mb = (size_t)b * HFULL * WFULL;

    float sum9 = 0.0f;
    for (int dh = 0; dh < 3; dh++) {
        for (int dw = 0; dw < 3; dw++) {
            int fi = li - 1 + dh, fj = lj - 1 + dw;
            if (fi >= 0 && fi < HLO && fj >= 0 && fj < WLO) {
                size_t base = mb + (size_t)(2 * fi) * WFULL + (2 * fj);
                sum9 += 0.25f * (mask[base] + mask[base + 1] + mask[base + WFULL] + mask[base + WFULL + 1]);
            }
        }
    }
    float mean = sum9 / 9.0f;
    g_mm[idx] = (mean == 1.0f) ? 1.0f : 0.0f;
}

// ===================================================================
// Kernel 2b: deterministic compaction of active columns
// ===================================================================
__global__ void __launch_bounds__(1024) compact_kernel()
{
    int b = blockIdx.x;
    int t = threadIdx.x;
    __shared__ int sc[1024];

    int base = t * 4;
    int loc[4];
    int cnt = 0;
#pragma unroll
    for (int i = 0; i < 4; i++) {
        loc[i] = (g_mm[b * LQ + base + i] != 0.0f) ? 1 : 0;
        cnt += loc[i];
    }
    sc[t] = cnt;
    __syncthreads();
    for (int off = 1; off < 1024; off <<= 1) {
        int v = (t >= off) ? sc[t - off] : 0;
        __syncthreads();
        sc[t] += v;
        __syncthreads();
    }
    int pos = sc[t] - cnt;
#pragma unroll
    for (int i = 0; i < 4; i++) {
        if (loc[i]) g_idx[b * LQ + (pos++)] = base + i;
    }
    if (t == 1023) {
        int total = sc[1023];
        int pad = (total + 15) & ~15;
        g_cnt[b * 2 + 0] = total;
        g_cnt[b * 2 + 1] = pad;
        for (int j = total; j < pad; j++) g_idx[b * LQ + j] = 0;
    }
}

// ===================================================================
// Kernel 2c: gather compacted V rows
// ===================================================================
__global__ void __launch_bounds__(576) vcomp_kernel()
{
    int b = blockIdx.y;
    int j = blockIdx.x;
    int cnt = g_cnt[b * 2 + 0];
    int pad = g_cnt[b * 2 + 1];
    if (j >= pad) return;
    int t = threadIdx.x;
    float v = 0.0f;
    if (j < cnt) {
        int l = g_idx[b * LQ + j];
        v = g_V[((size_t)b * LQ + l) * KC + t];
    }
    g_Vc[((size_t)b * LQ + j) * KC + t] = v;
}

// ===================================================================
// Kernel 3: score GEMM via warp-level bf16 mma.sync (3-pass exact-ish split)
//   dot = hi.hi + hi.lo + lo.hi  (lo.lo dropped, ~4e-6 relative)
// 128x128 CTA tile, 8 warps (2m x 4n), warp tile 64x32, BK=32,
// cp.async double-buffered SMEM (80B padded rows). Symmetric: upper block
// triangle only; epilogue writes both halves through SMEM.
// ===================================================================
#define SMSTRIDE 80     // bytes per smem row (64B data + 16B pad)
#define BUFBYTES 20480  // A(10240) + B(10240)

__global__ void __launch_bounds__(256) gemm_s_mma_kernel(float* __restrict__ out)
{
    if (blockIdx.x < blockIdx.y) return;

    __shared__ __align__(16) unsigned char smem_raw[2 * BUFBYTES];

    int t = threadIdx.x;
    int lane = t & 31;
    int wid = t >> 5;
    int warp_m = wid >> 2;       // 0..1
    int warp_n = wid & 3;        // 0..3
    int b = blockIdx.z;
    int p0 = blockIdx.y * 128;
    int q0 = blockIdx.x * 128;

    uint32_t sbase = smem_u32(smem_raw);
    const char* Abase = (const char*)g_Pbf + ((size_t)b * LQ + p0) * (KP * 2);
    const char* Bbase = (const char*)g_Pbf + ((size_t)b * LQ + q0) * (KP * 2);

    float acc[4][4][4];
#pragma unroll
    for (int i = 0; i < 4; i++)
#pragma unroll
        for (int j = 0; j < 4; j++)
#pragma unroll
            for (int k = 0; k < 4; k++) acc[i][j][k] = 0.0f;

    // stage chunk 'it' into buffer 'buf'
    auto stage = [&](int buf, int it) {
        int p = it / 18, kc = it % 18;
        int ha = (p == 2) ? 1 : 0;           // passes: (hi,hi), (hi,lo), (lo,hi)
        int hb = (p == 1) ? 1 : 0;
        size_t colA = (size_t)ha * (KC * 2) + (size_t)kc * 64;
        size_t colB = (size_t)hb * (KC * 2) + (size_t)kc * 64;
        uint32_t sA = sbase + buf * BUFBYTES;
        uint32_t sB = sA + 10240;
#pragma unroll
        for (int r = 0; r < 2; r++) {
            int id = t + r * 256;
            int row = id >> 2, u = id & 3;
            cp16(sA + row * SMSTRIDE + u * 16, Abase + (size_t)row * (KP * 2) + colA + u * 16);
            cp16(sB + row * SMSTRIDE + u * 16, Bbase + (size_t)row * (KP * 2) + colB + u * 16);
        }
    };

    // compute one BK=32 chunk from buffer 'buf'
    int lr = lane & 7, sel = lane >> 3;
    auto compute = [&](int buf) {
        uint32_t sA = sbase + buf * BUFBYTES;
        uint32_t sB = sA + 10240;
#pragma unroll
        for (int ks = 0; ks < 2; ks++) {
            uint32_t a[4][4];
#pragma unroll
            for (int mt = 0; mt < 4; mt++) {
                int row = warp_m * 64 + mt * 16 + lr + (sel & 1) * 8;
                uint32_t addr = sA + row * SMSTRIDE + ks * 32 + (sel >> 1) * 16;
                ldsm4(addr, a[mt][0], a[mt][1], a[mt][2], a[mt][3]);
            }
            uint32_t bf[2][4];
#pragma unroll
            for (int ntp = 0; ntp < 2; ntp++) {
                int row = warp_n * 32 + ntp * 16 + lr + (sel >> 1) * 8;
                uint32_t addr = sB + row * SMSTRIDE + ks * 32 + (sel & 1) * 16;
                ldsm4(addr, bf[ntp][0], bf[ntp][1], bf[ntp][2], bf[ntp][3]);
            }
#pragma unroll
            for (int mt = 0; mt < 4; mt++)
#pragma unroll
                for (int nt = 0; nt < 4; nt++) {
                    uint32_t b0 = bf[nt >> 1][(nt & 1) * 2];
                    uint32_t b1 = bf[nt >> 1][(nt & 1) * 2 + 1];
                    mma16816(acc[mt][nt][0], acc[mt][nt][1], acc[mt][nt][2], acc[mt][nt][3],
                             a[mt][0], a[mt][1], a[mt][2], a[mt][3], b0, b1);
                }
        }
    };

    stage(0, 0);
    cp_commit();
    for (int it = 0; it < 54; it++) {
        if (it + 1 < 54) {
            stage((it + 1) & 1, it + 1);
            cp_commit();
            cp_wait<1>();
        } else {
            cp_wait<0>();
        }
        __syncthreads();
        compute(it & 1);
        __syncthreads();
    }

    // ---- epilogue: two 64-row phases through SMEM; write both halves ----
    const float* __restrict__ inv = g_invden + b * LQ;
    float* __restrict__ Cb = out + YSZ + (size_t)b * LQ * LQ;
    float* S = (float*)smem_raw;   // 64 x 132 floats = 33792 B <= 40960

#pragma unroll
    for (int mhalf = 0; mhalf < 2; mhalf++) {
        __syncthreads();
        if (warp_m == mhalf) {
            int r0l = lane >> 2;
            int c0l = (lane & 3) * 2;
#pragma unroll
            for (int mt = 0; mt < 4; mt++)
#pragma unroll
                for (int nt = 0; nt < 4; nt++) {
                    int rr = mt * 16 + r0l;
                    int cc = warp_n * 32 + nt * 8 + c0l;
                    S[rr * 132 + cc]           = acc[mt][nt][0];
                    S[rr * 132 + cc + 1]       = acc[mt][nt][1];
                    S[(rr + 8) * 132 + cc]     = acc[mt][nt][2];
                    S[(rr + 8) * 132 + cc + 1] = acc[mt][nt][3];
                }
        }
        __syncthreads();
        // normal half: att[p0+mhalf*64+r][q0+c] = dot * inv[q0+c]
        {
            int r = t >> 2, cs = (t & 3) * 32;
            float* dst = Cb + (size_t)(p0 + mhalf * 64 + r) * LQ + q0 + cs;
            const float* sp = S + r * 132 + cs;
#pragma unroll 8
            for (int j = 0; j < 32; j++)
                dst[j] = sp[j] * __ldg(inv + q0 + cs + j);
        }
        // mirrored half: att[q0+c][p0+mhalf*64+r] = dot * inv[p0+mhalf*64+r]
        {
            int c = t >> 1, rs = (t & 1) * 32;
            float* dst = Cb + (size_t)(q0 + c) * LQ + p0 + mhalf * 64 + rs;
#pragma unroll 8
            for (int i = 0; i < 32; i++)
                dst[i] = S[(rs + i) * 132 + c] * __ldg(inv + p0 + mhalf * 64 + rs + i);
        }
    }
}

// ===================================================================
// Kernel 4: fuse + stable softmax (active columns) -> compacted U
// ===================================================================
__global__ void __launch_bounds__(256) fuse_softmax_kernel(const float* __restrict__ out)
{
    int b = blockIdx.y;
    int p = blockIdx.x;
    const float* __restrict__ ab = out + YSZ + (size_t)b * LQ * LQ;
    const int* __restrict__ idxb = g_idx + b * LQ;
    float* __restrict__ Up = g_U + ((size_t)b * LQ + p) * LQ;

    int cnt = g_cnt[b * 2 + 0];
    int pad = g_cnt[b * 2 + 1];

    int qi = p >> 6, qj = p & 63;
    int ap = (qj << 6) | qi;

    __shared__ float zbuf[LQ];
    __shared__ float red[256];

    int t = threadIdx.x;
    float lmax = (cnt < LQ) ? 0.0f : -3.4e38f;

    for (int j = t; j < pad; j += 256) {
        float z = 0.0f;
        if (j < cnt) {
            int l = __ldg(idxb + j);
            int ki = l >> 6, kj = l & 63;
            int bp = (kj << 6) | ki;
            float acc = 0.0f;
#pragma unroll
            for (int d2 = -1; d2 <= 1; d2++) {
                int aa = ap + d2;
                int bb = bp + d2;
                if ((unsigned)aa < LQ && (unsigned)bb < LQ) {
                    int u0 = ((aa & 63) << 6) | (aa >> 6);
                    int v0 = ((bb & 63) << 6) | (bb >> 6);
#pragma unroll
                    for (int d1 = -1; d1 <= 1; d1++) {
                        int uu = u0 + d1, vv = v0 + d1;
                        if ((unsigned)uu < LQ && (unsigned)vv < LQ)
                            acc += __ldg(ab + (size_t)uu * LQ + vv);
                    }
                }
            }
            z = acc * 10.0f;
            lmax = fmaxf(lmax, z);
        }
        zbuf[j] = z;
    }

    red[t] = lmax;
    __syncthreads();
    for (int off = 128; off >= 1; off >>= 1) {
        if (t < off) red[t] = fmaxf(red[t], red[t + off]);
        __syncthreads();
    }
    float rmax = red[0];
    __syncthreads();

    float lsum = 0.0f;
    for (int j = t; j < pad; j += 256) {
        float e = 0.0f;
        if (j < cnt) {
            e = expf(zbuf[j] - rmax);
            lsum += e;
        }
        zbuf[j] = e;
    }
    red[t] = lsum;
    __syncthreads();
    for (int off = 128; off >= 1; off >>= 1) {
        if (t < off) red[t] += red[t + off];
        __syncthreads();
    }
    float den = red[0] + (float)(LQ - cnt) * expf(-rmax);
    float invs = 1.0f / den;
    __syncthreads();

    for (int j = t; j < pad; j += 256) {
        Up[j] = zbuf[j] * invs;
    }
}

// ===================================================================
// Kernel 5: recon GEMM  Z = Ucomp @ Vcomp  (K bound from device)
// ===================================================================
__global__ void __launch_bounds__(256) gemm_z_kernel()
{
    int b = blockIdx.z;
    const float* __restrict__ A = g_U + (size_t)b * LQ * LQ;
    const float* __restrict__ Bm = g_Vc + (size_t)b * LQ * KC;
    float* __restrict__ Cb = g_Z + (size_t)b * LQ * KC;

    int kmax = g_cnt[b * 2 + 1];

    int p0 = blockIdx.y * 128;
    int n0 = blockIdx.x * 64;

    __shared__ float Asm[16][128];
    __shared__ float Bsm[16][64];

    int t = threadIdx.x;
    int tx = t & 15, ty = t >> 4;

    float acc[8][4] = {};

    for (int kt = 0; kt < kmax; kt += 16) {
#pragma unroll
        for (int r = 0; r < 2; r++) {
            int id = t + r * 256;
            int row = id >> 2, c4 = id & 3;
            float4 va = *(const float4*)(A + (size_t)(p0 + row) * LQ + kt + c4 * 4);
            Asm[c4 * 4 + 0][row] = va.x;
            Asm[c4 * 4 + 1][row] = va.y;
            Asm[c4 * 4 + 2][row] = va.z;
            Asm[c4 * 4 + 3][row] = va.w;
        }
        {
            int row = t >> 4, c4 = t & 15;
            float4 vb = *(const float4*)(Bm + (size_t)(kt + row) * KC + n0 + c4 * 4);
            Bsm[row][c4 * 4 + 0] = vb.x;
            Bsm[row][c4 * 4 + 1] = vb.y;
            Bsm[row][c4 * 4 + 2] = vb.z;
            Bsm[row][c4 * 4 + 3] = vb.w;
        }
        __syncthreads();
#pragma unroll
        for (int k = 0; k < 16; k++) {
            float a[8], bb[4];
            *(float4*)(a)     = *(const float4*)&Asm[k][ty * 8];
            *(float4*)(a + 4) = *(const float4*)&Asm[k][ty * 8 + 4];
            *(float4*)(bb)    = *(const float4*)&Bsm[k][tx * 4];
#pragma unroll
            for (int i = 0; i < 8; i++)
#pragma unroll
                for (int j = 0; j < 4; j++)
                    acc[i][j] += a[i] * bb[j];
        }
        __syncthreads();
    }

#pragma unroll
    for (int i = 0; i < 8; i++) {
        size_t off = (size_t)(p0 + ty * 8 + i) * KC + n0 + tx * 4;
        float4 w0 = make_float4(acc[i][0], acc[i][1], acc[i][2], acc[i][3]);
        *(float4*)(Cb + off) = w0;
    }
}

// ===================================================================
// Kernel 6: overlap-add (transposed conv gather)
// ===================================================================
__global__ void recon_kernel(float* __restrict__ out)
{
    int idx = blockIdx.x * blockDim.x + threadIdx.x;
    if (idx >= (int)YSZ) return;
    int c = idx & 63;
    int tmp = idx >> 6;
    int J = tmp & 127; tmp >>= 7;
    int I = tmp & 127;
    int b = tmp >> 7;

    int ri[2], rdh[2], rn = 0;
    if (I & 1) { ri[0] = (I - 1) >> 1; rdh[0] = 1; rn = 1; }
    else {
        ri[rn] = I >> 1; rdh[rn] = 0; rn++;
        if (I >= 2) { ri[rn] = (I >> 1) - 1; rdh[rn] = 2; rn++; }
    }
    int cj[2], cdw[2], cn = 0;
    if (J & 1) { cj[0] = (J - 1) >> 1; cdw[0] = 1; cn = 1; }
    else {
        cj[cn] = J >> 1; cdw[cn] = 0; cn++;
        if (J >= 2) { cj[cn] = (J >> 1) - 1; cdw[cn] = 2; cn++; }
    }

    const float* __restrict__ Zb = g_Z + (size_t)b * LQ * KC;
    float acc = 0.0f;
    for (int a = 0; a < rn; a++) {
        for (int bb = 0; bb < cn; bb++) {
            int l = ri[a] * 64 + cj[bb];
            int n = (rdh[a] * 3 + cdw[bb]) * 64 + c;
            acc += Zb[(size_t)l * KC + n];
        }
    }
    out[idx] = 0.25f * acc;
}

// ===================================================================
extern "C" void kernel_launch(void* const* d_in, const int* in_sizes, int n_in,
                              void* d_out, int out_size)
{
    const float* x    = (const float*)d_in[0];
    const float* mask = (const float*)d_in[1];
    float* out = (float*)d_out;
    (void)in_sizes; (void)n_in; (void)out_size;

    build_pv_kernel<<<dim3(LQ, BATCH), 576>>>(x);
    mm_kernel<<<(BATCH * LQ + 255) / 256, 256>>>(mask);
    compact_kernel<<<BATCH, 1024>>>();
    vcomp_kernel<<<dim3(LQ, BATCH), 576>>>();
    gemm_s_mma_kernel<<<dim3(32, 32, BATCH), 256>>>(out);
    fuse_softmax_kernel<<<dim3(LQ, BATCH), 256>>>(out);
    gemm_z_kernel<<<dim3(KC / 64, 32, BATCH), 256>>>();
    recon_kernel<<<(int)((YSZ + 255) / 256), 256>>>(out);
}

// round 6
// speedup vs baseline: 3.5907x; 1.2063x over previous
#include <cuda_runtime.h>
#include <cuda_bf16.h>
#include <cstdint>

// Problem constants
#define BATCH 2
#define HFULL 128
#define WFULL 128
#define CCH   64
#define HLO   64
#define WLO   64
#define LQ    4096          // HLO*WLO
#define KC    576           // 3*3*CCH
#define KP    1152          // split width: [hi(576) | lo(576)]

static const size_t YSZ = (size_t)BATCH * HFULL * WFULL * CCH; // y output floats

// -------- static device scratch --------
__device__ __align__(16) __nv_bfloat16 g_Pbf[(size_t)BATCH * LQ * KP];  // [hi|lo] per row
__device__ float g_V[(size_t)BATCH * LQ * KC];
__device__ float g_Z[(size_t)BATCH * LQ * KC];
__device__ __align__(16) __nv_bfloat16 g_Uhi[(size_t)BATCH * LQ * LQ];
__device__ __align__(16) __nv_bfloat16 g_Ulo[(size_t)BATCH * LQ * LQ];
__device__ __align__(16) __nv_bfloat16 g_VhiT[(size_t)BATCH * KC * LQ];  // [n][j]
__device__ __align__(16) __nv_bfloat16 g_VloT[(size_t)BATCH * KC * LQ];
__device__ float g_invden[BATCH * LQ];
__device__ float g_mm[BATCH * LQ];
__device__ int   g_idx[BATCH * LQ];
__device__ int   g_cnt[BATCH * 2];

// ---------------- helpers (baseline sm_80-era PTX, safe on compute_103) ----
__device__ __forceinline__ uint32_t smem_u32(const void* p) {
    uint32_t a;
    asm("{ .reg .u64 t; cvta.to.shared.u64 t, %1; cvt.u32.u64 %0, t; }" : "=r"(a) : "l"(p));
    return a;
}
__device__ __forceinline__ void cp16(uint32_t dst, const void* src) {
    asm volatile("cp.async.cg.shared.global [%0], [%1], 16;" :: "r"(dst), "l"(src));
}
__device__ __forceinline__ void cp_commit() {
    asm volatile("cp.async.commit_group;");
}
template<int N> __device__ __forceinline__ void cp_wait() {
    asm volatile("cp.async.wait_group %0;" :: "n"(N));
}
__device__ __forceinline__ void ldsm4(uint32_t a, uint32_t& r0, uint32_t& r1, uint32_t& r2, uint32_t& r3) {
    asm volatile("ldmatrix.sync.aligned.m8n8.x4.shared.b16 {%0,%1,%2,%3}, [%4];"
                 : "=r"(r0), "=r"(r1), "=r"(r2), "=r"(r3) : "r"(a));
}
__device__ __forceinline__ void ldsm2(uint32_t a, uint32_t& r0, uint32_t& r1) {
    asm volatile("ldmatrix.sync.aligned.m8n8.x2.shared.b16 {%0,%1}, [%2];"
                 : "=r"(r0), "=r"(r1) : "r"(a));
}
__device__ __forceinline__ void mma16816(float& c0, float& c1, float& c2, float& c3,
                                         uint32_t a0, uint32_t a1, uint32_t a2, uint32_t a3,
                                         uint32_t b0, uint32_t b1) {
    asm volatile("mma.sync.aligned.m16n8k16.row.col.f32.bf16.bf16.f32 "
                 "{%0,%1,%2,%3}, {%4,%5,%6,%7}, {%8,%9}, {%0,%1,%2,%3};"
                 : "+f"(c0), "+f"(c1), "+f"(c2), "+f"(c3)
                 : "r"(a0), "r"(a1), "r"(a2), "r"(a3), "r"(b0), "r"(b1));
}

// XOR-swizzled smem offset for 64B rows, 16B chunks: banks distinct over 8 rows
__device__ __forceinline__ uint32_t sw64(int row, int chunk) {
    return (uint32_t)(row * 64 + 16 * (chunk ^ ((row >> 1) & 3)));
}

// ===================================================================
// Kernel 1: build split-bf16 P, V (raw patches), invden
// ===================================================================
__global__ void __launch_bounds__(576) build_pv_kernel(const float* __restrict__ x)
{
    int b = blockIdx.y;
    int l = blockIdx.x;
    int li = l >> 6, lj = l & 63;
    int t = threadIdx.x;
    int c = t & 63;
    int g = t >> 6;
    int dh = g / 3, dw = g % 3;

    const size_t xb = (size_t)b * HFULL * WFULL * CCH;

    int fi = li - 1 + dh;
    int fj = lj - 1 + dw;
    float pv = 0.0f;
    if (fi >= 0 && fi < HLO && fj >= 0 && fj < WLO) {
        size_t base = xb + (size_t)(2 * fi) * (WFULL * CCH) + (size_t)(2 * fj) * CCH + c;
        pv = 0.25f * (x[base] + x[base + CCH] + x[base + WFULL * CCH] + x[base + WFULL * CCH + CCH]);
    }
    __nv_bfloat16 hi = __float2bfloat16(pv);
    float lof = pv - __bfloat162float(hi);
    __nv_bfloat16 lo = __float2bfloat16(lof);
    size_t rb = ((size_t)b * LQ + l) * KP;
    g_Pbf[rb + t] = hi;
    g_Pbf[rb + KC + t] = lo;

    int xr = 2 * li + dh;
    int xc = 2 * lj + dw;
    float vv = 0.0f;
    if (xr < HFULL && xc < WFULL) {
        vv = x[xb + (size_t)xr * (WFULL * CCH) + (size_t)xc * CCH + c];
    }
    g_V[((size_t)b * LQ + l) * KC + t] = vv;

    __shared__ float s[576];
    s[t] = pv * pv;
    __syncthreads();
    if (t < 64) s[t] += s[t + 512];
    __syncthreads();
    for (int off = 256; off >= 1; off >>= 1) {
        if (t < off) s[t] += s[t + off];
        __syncthreads();
    }
    if (t == 0) {
        float nrm = sqrtf(s[0]);
        g_invden[b * LQ + l] = 1.0f / fmaxf(nrm, 1e-4f);
    }
}

// ===================================================================
// Kernel 2: mask gate
// ===================================================================
__global__ void mm_kernel(const float* __restrict__ mask)
{
    int idx = blockIdx.x * blockDim.x + threadIdx.x;
    if (idx >= BATCH * LQ) return;
    int b = idx / LQ;
    int l = idx % LQ;
    int li = l >> 6, lj = l & 63;
    const size_t mb = (size_t)b * HFULL * WFULL;

    float sum9 = 0.0f;
    for (int dh = 0; dh < 3; dh++) {
        for (int dw = 0; dw < 3; dw++) {
            int fi = li - 1 + dh, fj = lj - 1 + dw;
            if (fi >= 0 && fi < HLO && fj >= 0 && fj < WLO) {
                size_t base = mb + (size_t)(2 * fi) * WFULL + (2 * fj);
                sum9 += 0.25f * (mask[base] + mask[base + 1] + mask[base + WFULL] + mask[base + WFULL + 1]);
            }
        }
    }
    float mean = sum9 / 9.0f;
    g_mm[idx] = (mean == 1.0f) ? 1.0f : 0.0f;
}

// ===================================================================
// Kernel 2b: deterministic compaction of active columns (pad to 64)
// ===================================================================
__global__ void __launch_bounds__(1024) compact_kernel()
{
    int b = blockIdx.x;
    int t = threadIdx.x;
    __shared__ int sc[1024];

    int base = t * 4;
    int loc[4];
    int cnt = 0;
#pragma unroll
    for (int i = 0; i < 4; i++) {
        loc[i] = (g_mm[b * LQ + base + i] != 0.0f) ? 1 : 0;
        cnt += loc[i];
    }
    sc[t] = cnt;
    __syncthreads();
    for (int off = 1; off < 1024; off <<= 1) {
        int v = (t >= off) ? sc[t - off] : 0;
        __syncthreads();
        sc[t] += v;
        __syncthreads();
    }
    int pos = sc[t] - cnt;
#pragma unroll
    for (int i = 0; i < 4; i++) {
        if (loc[i]) g_idx[b * LQ + (pos++)] = base + i;
    }
    if (t == 1023) {
        int total = sc[1023];
        int pad = (total + 63) & ~63;
        g_cnt[b * 2 + 0] = total;
        g_cnt[b * 2 + 1] = pad;
        for (int j = total; j < pad; j++) g_idx[b * LQ + j] = 0;
    }
}

// ===================================================================
// Kernel 2c: gather compacted V rows TRANSPOSED, split bf16
// block j (active col), 576 threads over n: VT[n][j]
// ===================================================================
__global__ void __launch_bounds__(576) vcompT_kernel()
{
    int b = blockIdx.y;
    int j = blockIdx.x;
    int cnt = g_cnt[b * 2 + 0];
    int pad = g_cnt[b * 2 + 1];
    if (j >= pad) return;
    int n = threadIdx.x;
    float v = 0.0f;
    if (j < cnt) {
        int l = g_idx[b * LQ + j];
        v = g_V[((size_t)b * LQ + l) * KC + n];
    }
    __nv_bfloat16 hi = __float2bfloat16(v);
    float lof = v - __bfloat162float(hi);
    size_t o = ((size_t)b * KC + n) * LQ + j;
    g_VhiT[o] = hi;
    g_VloT[o] = __float2bfloat16(lof);
}

// ===================================================================
// Kernel 3: score GEMM via bf16 mma.sync, 3-pass split, block-triangle
// symmetric. 128x128 tile, 8 warps (2x4), warp 64x32, BK=32,
// 3-stage cp.async ring (1 sync/iter), XOR-swizzled 64B smem rows.
// ===================================================================
#define SBUF 16384   // per-stage bytes: A 8KB + B 8KB

__global__ void __launch_bounds__(256) gemm_s_mma_kernel(float* __restrict__ out)
{
    if (blockIdx.x < blockIdx.y) return;

    __shared__ __align__(16) unsigned char smem_raw[3 * SBUF];  // 48KB exactly

    int t = threadIdx.x;
    int lane = t & 31;
    int wid = t >> 5;
    int warp_m = wid >> 2;       // 0..1
    int warp_n = wid & 3;        // 0..3
    int b = blockIdx.z;
    int p0 = blockIdx.y * 128;
    int q0 = blockIdx.x * 128;

    uint32_t sbase = smem_u32(smem_raw);
    const char* Abase = (const char*)g_Pbf + ((size_t)b * LQ + p0) * (KP * 2);
    const char* Bbase = (const char*)g_Pbf + ((size_t)b * LQ + q0) * (KP * 2);

    float acc[4][4][4];
#pragma unroll
    for (int i = 0; i < 4; i++)
#pragma unroll
        for (int j = 0; j < 4; j++)
#pragma unroll
            for (int k = 0; k < 4; k++) acc[i][j][k] = 0.0f;

    const int NIT = 54;  // 3 passes x 18 chunks of 32 bf16 (64B)
    auto stage = [&](int buf, int it) {
        int p = it / 18, kc = it % 18;
        int ha = (p == 2) ? 1 : 0;           // passes: (hi,hi), (hi,lo), (lo,hi)
        int hb = (p == 1) ? 1 : 0;
        size_t colA = (size_t)ha * (KC * 2) + (size_t)kc * 64;
        size_t colB = (size_t)hb * (KC * 2) + (size_t)kc * 64;
        uint32_t sA = sbase + buf * SBUF;
        uint32_t sB = sA + 8192;
#pragma unroll
        for (int r = 0; r < 2; r++) {
            int id = t + r * 256;
            int row = id >> 2, u = id & 3;
            cp16(sA + sw64(row, u), Abase + (size_t)row * (KP * 2) + colA + u * 16);
            cp16(sB + sw64(row, u), Bbase + (size_t)row * (KP * 2) + colB + u * 16);
        }
    };

    int lr = lane & 7, sel = lane >> 3;
    auto compute = [&](int buf) {
        uint32_t sA = sbase + buf * SBUF;
        uint32_t sB = sA + 8192;
#pragma unroll
        for (int ks = 0; ks < 2; ks++) {
            uint32_t a[4][4];
#pragma unroll
            for (int mt = 0; mt < 4; mt++) {
                int row = warp_m * 64 + mt * 16 + lr + (sel & 1) * 8;
                int cc = ks * 2 + (sel >> 1);
                ldsm4(sA + sw64(row, cc), a[mt][0], a[mt][1], a[mt][2], a[mt][3]);
            }
            uint32_t bf[2][4];
#pragma unroll
            for (int ntp = 0; ntp < 2; ntp++) {
                int row = warp_n * 32 + ntp * 16 + lr + (sel >> 1) * 8;
                int cc = ks * 2 + (sel & 1);
                ldsm4(sB + sw64(row, cc), bf[ntp][0], bf[ntp][1], bf[ntp][2], bf[ntp][3]);
            }
#pragma unroll
            for (int mt = 0; mt < 4; mt++)
#pragma unroll
                for (int nt = 0; nt < 4; nt++) {
                    uint32_t b0 = bf[nt >> 1][(nt & 1) * 2];
                    uint32_t b1 = bf[nt >> 1][(nt & 1) * 2 + 1];
                    mma16816(acc[mt][nt][0], acc[mt][nt][1], acc[mt][nt][2], acc[mt][nt][3],
                             a[mt][0], a[mt][1], a[mt][2], a[mt][3], b0, b1);
                }
        }
    };

    stage(0, 0);
    cp_commit();
    for (int it = 0; it < NIT; it++) {
        if (it + 1 < NIT) {
            stage((it + 1) % 3, it + 1);
            cp_commit();
            cp_wait<1>();
        } else {
            cp_wait<0>();
        }
        __syncthreads();
        compute(it % 3);
    }

    // ---- epilogue: two 64-row phases through SMEM; write both halves ----
    const float* __restrict__ inv = g_invden + b * LQ;
    float* __restrict__ Cb = out + YSZ + (size_t)b * LQ * LQ;
    float* S = (float*)smem_raw;   // 64 x 132 floats = 33792 B <= 48KB

#pragma unroll
    for (int mhalf = 0; mhalf < 2; mhalf++) {
        __syncthreads();
        if (warp_m == mhalf) {
            int r0l = lane >> 2;
            int c0l = (lane & 3) * 2;
#pragma unroll
            for (int mt = 0; mt < 4; mt++)
#pragma unroll
                for (int nt = 0; nt < 4; nt++) {
                    int rr = mt * 16 + r0l;
                    int cc = warp_n * 32 + nt * 8 + c0l;
                    S[rr * 132 + cc]           = acc[mt][nt][0];
                    S[rr * 132 + cc + 1]       = acc[mt][nt][1];
                    S[(rr + 8) * 132 + cc]     = acc[mt][nt][2];
                    S[(rr + 8) * 132 + cc + 1] = acc[mt][nt][3];
                }
        }
        __syncthreads();
        // normal half: att[p0+mhalf*64+r][q0+c] = dot * inv[q0+c]
        {
            int r = t >> 2, cs = (t & 3) * 32;
            float* dst = Cb + (size_t)(p0 + mhalf * 64 + r) * LQ + q0 + cs;
            const float* sp = S + r * 132 + cs;
#pragma unroll 8
            for (int j = 0; j < 32; j++)
                dst[j] = sp[j] * __ldg(inv + q0 + cs + j);
        }
        // mirrored half: att[q0+c][p0+mhalf*64+r] = dot * inv[p0+mhalf*64+r]
        {
            int c = t >> 1, rs = (t & 1) * 32;
            float* dst = Cb + (size_t)(q0 + c) * LQ + p0 + mhalf * 64 + rs;
#pragma unroll 8
            for (int i = 0; i < 32; i++)
                dst[i] = S[(rs + i) * 132 + c] * __ldg(inv + p0 + mhalf * 64 + rs + i);
        }
    }
}

// ===================================================================
// Kernel 4: fuse + stable softmax (active columns) -> split-bf16 U
// ===================================================================
__global__ void __launch_bounds__(256) fuse_softmax_kernel(const float* __restrict__ out)
{
    int b = blockIdx.y;
    int p = blockIdx.x;
    const float* __restrict__ ab = out + YSZ + (size_t)b * LQ * LQ;
    const int* __restrict__ idxb = g_idx + b * LQ;
    __nv_bfloat16* __restrict__ Uhp = g_Uhi + ((size_t)b * LQ + p) * LQ;
    __nv_bfloat16* __restrict__ Ulp = g_Ulo + ((size_t)b * LQ + p) * LQ;

    int cnt = g_cnt[b * 2 + 0];
    int pad = g_cnt[b * 2 + 1];

    int qi = p >> 6, qj = p & 63;
    int ap = (qj << 6) | qi;

    __shared__ float zbuf[LQ];
    __shared__ float red[256];

    int t = threadIdx.x;
    float lmax = (cnt < LQ) ? 0.0f : -3.4e38f;

    for (int j = t; j < pad; j += 256) {
        float z = 0.0f;
        if (j < cnt) {
            int l = __ldg(idxb + j);
            int ki = l >> 6, kj = l & 63;
            int bp = (kj << 6) | ki;
            float acc = 0.0f;
#pragma unroll
            for (int d2 = -1; d2 <= 1; d2++) {
                int aa = ap + d2;
                int bb = bp + d2;
                if ((unsigned)aa < LQ && (unsigned)bb < LQ) {
                    int u0 = ((aa & 63) << 6) | (aa >> 6);
                    int v0 = ((bb & 63) << 6) | (bb >> 6);
#pragma unroll
                    for (int d1 = -1; d1 <= 1; d1++) {
                        int uu = u0 + d1, vv = v0 + d1;
                        if ((unsigned)uu < LQ && (unsigned)vv < LQ)
                            acc += __ldg(ab + (size_t)uu * LQ + vv);
                    }
                }
            }
            z = acc * 10.0f;
            lmax = fmaxf(lmax, z);
        }
        zbuf[j] = z;
    }

    red[t] = lmax;
    __syncthreads();
    for (int off = 128; off >= 1; off >>= 1) {
        if (t < off) red[t] = fmaxf(red[t], red[t + off]);
        __syncthreads();
    }
    float rmax = red[0];
    __syncthreads();

    float lsum = 0.0f;
    for (int j = t; j < pad; j += 256) {
        float e = 0.0f;
        if (j < cnt) {
            e = expf(zbuf[j] - rmax);
            lsum += e;
        }
        zbuf[j] = e;
    }
    red[t] = lsum;
    __syncthreads();
    for (int off = 128; off >= 1; off >>= 1) {
        if (t < off) red[t] += red[t + off];
        __syncthreads();
    }
    float den = red[0] + (float)(LQ - cnt) * expf(-rmax);
    float invs = 1.0f / den;
    __syncthreads();

    for (int j = t; j < pad; j += 256) {
        float val = zbuf[j] * invs;
        __nv_bfloat16 hi = __float2bfloat16(val);
        Uhp[j] = hi;
        Ulp[j] = __float2bfloat16(val - __bfloat162float(hi));
    }
}

// ===================================================================
// Kernel 5: recon GEMM via bf16 mma.sync, 3-pass split
// Z[p][n] = sum_j U[p][j] * VT[n][j], K = pad (runtime, 64-aligned)
// 128x96 tile, 8 warps (2x4), warp 64x24, BK=32, 3-stage ring.
// ===================================================================
#define ZBUFA 8192
#define ZBUFB 6144
#define ZBUF  (ZBUFA + ZBUFB)

__global__ void __launch_bounds__(256) gemm_z_mma_kernel()
{
    __shared__ __align__(16) unsigned char smem_raw[3 * ZBUF];  // 42KB

    int t = threadIdx.x;
    int lane = t & 31;
    int wid = t >> 5;
    int warp_m = wid >> 2;       // 0..1
    int warp_n = wid & 3;        // 0..3
    int b = blockIdx.z;
    int p0 = blockIdx.y * 128;
    int n0 = blockIdx.x * 96;

    int kmax = g_cnt[b * 2 + 1];            // 64-aligned
    int nk = kmax >> 5;                      // BK=32 chunks per pass
    int NIT = 3 * nk;

    uint32_t sbase = smem_u32(smem_raw);
    const __nv_bfloat16* Ah = g_Uhi + ((size_t)b * LQ + p0) * LQ;
    const __nv_bfloat16* Al = g_Ulo + ((size_t)b * LQ + p0) * LQ;
    const __nv_bfloat16* Bh = g_VhiT + ((size_t)b * KC + n0) * LQ;
    const __nv_bfloat16* Bl = g_VloT + ((size_t)b * KC + n0) * LQ;

    float acc[4][3][4];
#pragma unroll
    for (int i = 0; i < 4; i++)
#pragma unroll
        for (int j = 0; j < 3; j++)
#pragma unroll
            for (int k = 0; k < 4; k++) acc[i][j][k] = 0.0f;

    auto stage = [&](int buf, int it) {
        int p = it / nk, kc = it % nk;
        const char* As = (const char*)((p == 2) ? Al : Ah);
        const char* Bs = (const char*)((p == 1) ? Bl : Bh);
        size_t col = (size_t)kc * 64;     // bytes
        uint32_t sA = sbase + buf * ZBUF;
        uint32_t sB = sA + ZBUFA;
        for (int i = t; i < 896; i += 256) {
            if (i < 512) {
                int row = i >> 2, u = i & 3;
                cp16(sA + sw64(row, u), As + (size_t)row * (LQ * 2) + col + u * 16);
            } else {
                int j = i - 512;
                int row = j >> 2, u = j & 3;
                cp16(sB + sw64(row, u), Bs + (size_t)row * (LQ * 2) + col + u * 16);
            }
        }
    };

    int lr = lane & 7, sel = lane >> 3;
    int lr2 = lane & 7, half2 = (lane >> 3) & 1;
    auto compute = [&](int buf) {
        uint32_t sA = sbase + buf * ZBUF;
        uint32_t sB = sA + ZBUFA;
#pragma unroll
        for (int ks = 0; ks < 2; ks++) {
            uint32_t a[4][4];
#pragma unroll
            for (int mt = 0; mt < 4; mt++) {
                int row = warp_m * 64 + mt * 16 + lr + (sel & 1) * 8;
                int cc = ks * 2 + (sel >> 1);
                ldsm4(sA + sw64(row, cc), a[mt][0], a[mt][1], a[mt][2], a[mt][3]);
            }
            uint32_t b4[4], b2[2];
            {
                int row = warp_n * 24 + lr + (sel >> 1) * 8;
                int cc = ks * 2 + (sel & 1);
                ldsm4(sB + sw64(row, cc), b4[0], b4[1], b4[2], b4[3]);
            }
            {
                int row = warp_n * 24 + 16 + lr2;
                int cc = ks * 2 + half2;
                ldsm2(sB + sw64(row, cc), b2[0], b2[1]);
            }
#pragma unroll
            for (int mt = 0; mt < 4; mt++) {
                mma16816(acc[mt][0][0], acc[mt][0][1], acc[mt][0][2], acc[mt][0][3],
                         a[mt][0], a[mt][1], a[mt][2], a[mt][3], b4[0], b4[1]);
                mma16816(acc[mt][1][0], acc[mt][1][1], acc[mt][1][2], acc[mt][1][3],
                         a[mt][0], a[mt][1], a[mt][2], a[mt][3], b4[2], b4[3]);
                mma16816(acc[mt][2][0], acc[mt][2][1], acc[mt][2][2], acc[mt][2][3],
                         a[mt][0], a[mt][1], a[mt][2], a[mt][3], b2[0], b2[1]);
            }
        }
    };

    stage(0, 0);
    cp_commit();
    for (int it = 0; it < NIT; it++) {
        if (it + 1 < NIT) {
            stage((it + 1) % 3, it + 1);
            cp_commit();
            cp_wait<1>();
        } else {
            cp_wait<0>();
        }
        __syncthreads();
        compute(it % 3);
    }

    // epilogue: direct float2 stores to g_Z
    float* __restrict__ Zb = g_Z + (size_t)b * LQ * KC;
    int r0l = lane >> 2;
    int c0l = (lane & 3) * 2;
#pragma unroll
    for (int mt = 0; mt < 4; mt++)
#pragma unroll
        for (int nt = 0; nt < 3; nt++) {
            int row = p0 + warp_m * 64 + mt * 16 + r0l;
            int col = n0 + warp_n * 24 + nt * 8 + c0l;
            *(float2*)(Zb + (size_t)row * KC + col) =
                make_float2(acc[mt][nt][0], acc[mt][nt][1]);
            *(float2*)(Zb + (size_t)(row + 8) * KC + col) =
                make_float2(acc[mt][nt][2], acc[mt][nt][3]);
        }
}

// ===================================================================
// Kernel 6: overlap-add (transposed conv gather)
// ===================================================================
__global__ void recon_kernel(float* __restrict__ out)
{
    int idx = blockIdx.x * blockDim.x + threadIdx.x;
    if (idx >= (int)YSZ) return;
    int c = idx & 63;
    int tmp = idx >> 6;
    int J = tmp & 127; tmp >>= 7;
    int I = tmp & 127;
    int b = tmp >> 7;

    int ri[2], rdh[2], rn = 0;
    if (I & 1) { ri[0] = (I - 1) >> 1; rdh[0] = 1; rn = 1; }
    else {
        ri[rn] = I >> 1; rdh[rn] = 0; rn++;
        if (I >= 2) { ri[rn] = (I >> 1) - 1; rdh[rn] = 2; rn++; }
    }
    int cj[2], cdw[2], cn = 0;
    if (J & 1) { cj[0] = (J - 1) >> 1; cdw[0] = 1; cn = 1; }
    else {
        cj[cn] = J >> 1; cdw[cn] = 0; cn++;
        if (J >= 2) { cj[cn] = (J >> 1) - 1; cdw[cn] = 2; cn++; }
    }

    const float* __restrict__ Zb = g_Z + (size_t)b * LQ * KC;
    float acc = 0.0f;
    for (int a = 0; a < rn; a++) {
        for (int bb = 0; bb < cn; bb++) {
            int l = ri[a] * 64 + cj[bb];
            int n = (rdh[a] * 3 + cdw[bb]) * 64 + c;
            acc += Zb[(size_t)l * KC + n];
        }
    }
    out[idx] = 0.25f * acc;
}

// ===================================================================
extern "C" void kernel_launch(void* const* d_in, const int* in_sizes, int n_in,
                              void* d_out, int out_size)
{
    const float* x    = (const float*)d_in[0];
    const float* mask = (const float*)d_in[1];
    float* out = (float*)d_out;
    (void)in_sizes; (void)n_in; (void)out_size;

    build_pv_kernel<<<dim3(LQ, BATCH), 576>>>(x);
    mm_kernel<<<(BATCH * LQ + 255) / 256, 256>>>(mask);
    compact_kernel<<<BATCH, 1024>>>();
    vcompT_kernel<<<dim3(LQ, BATCH), 576>>>();
    gemm_s_mma_kernel<<<dim3(32, 32, BATCH), 256>>>(out);
    fuse_softmax_kernel<<<dim3(LQ, BATCH), 256>>>(out);
    gemm_z_mma_kernel<<<dim3(6, 32, BATCH), 256>>>();
    recon_kernel<<<(int)((YSZ + 255) / 256), 256>>>(out);
}

// round 7
// speedup vs baseline: 3.9552x; 1.1015x over previous
#include <cuda_runtime.h>
#include <cuda_bf16.h>
#include <cstdint>

// Problem constants
#define BATCH 2
#define HFULL 128
#define WFULL 128
#define CCH   64
#define HLO   64
#define WLO   64
#define LQ    4096          // HLO*WLO
#define KC    576           // 3*3*CCH
#define KP    1152          // split width: [hi(576) | lo(576)]

static const size_t YSZ = (size_t)BATCH * HFULL * WFULL * CCH; // y output floats

// -------- static device scratch --------
__device__ __align__(16) __nv_bfloat16 g_Pbf[(size_t)BATCH * LQ * KP];  // [hi|lo] per row
__device__ float g_V[(size_t)BATCH * LQ * KC];
__device__ float g_Z[(size_t)BATCH * LQ * KC];
__device__ __align__(16) __nv_bfloat16 g_Uhi[(size_t)BATCH * LQ * LQ];
__device__ __align__(16) __nv_bfloat16 g_Ulo[(size_t)BATCH * LQ * LQ];
__device__ __align__(16) __nv_bfloat16 g_VhiT[(size_t)BATCH * KC * LQ];  // [n][j]
__device__ __align__(16) __nv_bfloat16 g_VloT[(size_t)BATCH * KC * LQ];
__device__ float g_invden[BATCH * LQ];
__device__ float g_mm[BATCH * LQ];
__device__ int   g_idx[BATCH * LQ];
__device__ int   g_cnt[BATCH * 2];

// ---------------- helpers (baseline sm_80-era PTX, safe on compute_103) ----
__device__ __forceinline__ uint32_t smem_u32(const void* p) {
    uint32_t a;
    asm("{ .reg .u64 t; cvta.to.shared.u64 t, %1; cvt.u32.u64 %0, t; }" : "=r"(a) : "l"(p));
    return a;
}
__device__ __forceinline__ void cp16(uint32_t dst, const void* src) {
    asm volatile("cp.async.cg.shared.global [%0], [%1], 16;" :: "r"(dst), "l"(src));
}
__device__ __forceinline__ void cp_commit() {
    asm volatile("cp.async.commit_group;");
}
template<int N> __device__ __forceinline__ void cp_wait() {
    asm volatile("cp.async.wait_group %0;" :: "n"(N));
}
__device__ __forceinline__ void ldsm4(uint32_t a, uint32_t& r0, uint32_t& r1, uint32_t& r2, uint32_t& r3) {
    asm volatile("ldmatrix.sync.aligned.m8n8.x4.shared.b16 {%0,%1,%2,%3}, [%4];"
                 : "=r"(r0), "=r"(r1), "=r"(r2), "=r"(r3) : "r"(a));
}
__device__ __forceinline__ void ldsm2(uint32_t a, uint32_t& r0, uint32_t& r1) {
    asm volatile("ldmatrix.sync.aligned.m8n8.x2.shared.b16 {%0,%1}, [%2];"
                 : "=r"(r0), "=r"(r1) : "r"(a));
}
__device__ __forceinline__ void mma16816(float& c0, float& c1, float& c2, float& c3,
                                         uint32_t a0, uint32_t a1, uint32_t a2, uint32_t a3,
                                         uint32_t b0, uint32_t b1) {
    asm volatile("mma.sync.aligned.m16n8k16.row.col.f32.bf16.bf16.f32 "
                 "{%0,%1,%2,%3}, {%4,%5,%6,%7}, {%8,%9}, {%0,%1,%2,%3};"
                 : "+f"(c0), "+f"(c1), "+f"(c2), "+f"(c3)
                 : "r"(a0), "r"(a1), "r"(a2), "r"(a3), "r"(b0), "r"(b1));
}

// XOR-swizzled smem offset for 32B rows (BK=16 bf16), 16B chunks:
// banks distinct within each 8-row ldmatrix phase.
__device__ __forceinline__ uint32_t sw32(int row, int chunk) {
    return (uint32_t)(row * 32 + 16 * (chunk ^ ((row >> 2) & 1)));
}

// ===================================================================
// Kernel 1: build split-bf16 P, V (raw patches), invden
// ===================================================================
__global__ void __launch_bounds__(576) build_pv_kernel(const float* __restrict__ x)
{
    int b = blockIdx.y;
    int l = blockIdx.x;
    int li = l >> 6, lj = l & 63;
    int t = threadIdx.x;
    int c = t & 63;
    int g = t >> 6;
    int dh = g / 3, dw = g % 3;

    const size_t xb = (size_t)b * HFULL * WFULL * CCH;

    int fi = li - 1 + dh;
    int fj = lj - 1 + dw;
    float pv = 0.0f;
    if (fi >= 0 && fi < HLO && fj >= 0 && fj < WLO) {
        size_t base = xb + (size_t)(2 * fi) * (WFULL * CCH) + (size_t)(2 * fj) * CCH + c;
        pv = 0.25f * (x[base] + x[base + CCH] + x[base + WFULL * CCH] + x[base + WFULL * CCH + CCH]);
    }
    __nv_bfloat16 hi = __float2bfloat16(pv);
    float lof = pv - __bfloat162float(hi);
    __nv_bfloat16 lo = __float2bfloat16(lof);
    size_t rb = ((size_t)b * LQ + l) * KP;
    g_Pbf[rb + t] = hi;
    g_Pbf[rb + KC + t] = lo;

    int xr = 2 * li + dh;
    int xc = 2 * lj + dw;
    float vv = 0.0f;
    if (xr < HFULL && xc < WFULL) {
        vv = x[xb + (size_t)xr * (WFULL * CCH) + (size_t)xc * CCH + c];
    }
    g_V[((size_t)b * LQ + l) * KC + t] = vv;

    // norm reduce: warp shuffles + tiny cross-warp
    float sq = pv * pv;
#pragma unroll
    for (int off = 16; off >= 1; off >>= 1)
        sq += __shfl_xor_sync(0xffffffffu, sq, off);
    __shared__ float ws[18];
    int warp = t >> 5, lane = t & 31;
    if (lane == 0) ws[warp] = sq;
    __syncthreads();
    if (t == 0) {
        float s = 0.0f;
#pragma unroll
        for (int w = 0; w < 18; w++) s += ws[w];
        g_invden[b * LQ + l] = 1.0f / fmaxf(sqrtf(s), 1e-4f);
    }
}

// ===================================================================
// Kernel 2: mask gate
// ===================================================================
__global__ void mm_kernel(const float* __restrict__ mask)
{
    int idx = blockIdx.x * blockDim.x + threadIdx.x;
    if (idx >= BATCH * LQ) return;
    int b = idx / LQ;
    int l = idx % LQ;
    int li = l >> 6, lj = l & 63;
    const size_t mb = (size_t)b * HFULL * WFULL;

    float sum9 = 0.0f;
    for (int dh = 0; dh < 3; dh++) {
        for (int dw = 0; dw < 3; dw++) {
            int fi = li - 1 + dh, fj = lj - 1 + dw;
            if (fi >= 0 && fi < HLO && fj >= 0 && fj < WLO) {
                size_t base = mb + (size_t)(2 * fi) * WFULL + (2 * fj);
                sum9 += 0.25f * (mask[base] + mask[base + 1] + mask[base + WFULL] + mask[base + WFULL + 1]);
            }
        }
    }
    float mean = sum9 / 9.0f;
    g_mm[idx] = (mean == 1.0f) ? 1.0f : 0.0f;
}

// ===================================================================
// Kernel 2b: deterministic compaction of active columns (pad to 64)
// ===================================================================
__global__ void __launch_bounds__(1024) compact_kernel()
{
    int b = blockIdx.x;
    int t = threadIdx.x;
    __shared__ int sc[1024];

    int base = t * 4;
    int loc[4];
    int cnt = 0;
#pragma unroll
    for (int i = 0; i < 4; i++) {
        loc[i] = (g_mm[b * LQ + base + i] != 0.0f) ? 1 : 0;
        cnt += loc[i];
    }
    sc[t] = cnt;
    __syncthreads();
    for (int off = 1; off < 1024; off <<= 1) {
        int v = (t >= off) ? sc[t - off] : 0;
        __syncthreads();
        sc[t] += v;
        __syncthreads();
    }
    int pos = sc[t] - cnt;
#pragma unroll
    for (int i = 0; i < 4; i++) {
        if (loc[i]) g_idx[b * LQ + (pos++)] = base + i;
    }
    if (t == 1023) {
        int total = sc[1023];
        int pad = (total + 63) & ~63;
        g_cnt[b * 2 + 0] = total;
        g_cnt[b * 2 + 1] = pad;
        for (int j = total; j < pad; j++) g_idx[b * LQ + j] = 0;
    }
}

// ===================================================================
// Kernel 2c: compacted-transposed split V: VT[n][j]
// grid(KC, BATCH), block 256; j loop -> coalesced writes
// ===================================================================
__global__ void __launch_bounds__(256) vcompT_kernel()
{
    int b = blockIdx.y;
    int n = blockIdx.x;
    int cnt = g_cnt[b * 2 + 0];
    int pad = g_cnt[b * 2 + 1];
    const int* __restrict__ idxb = g_idx + b * LQ;
    const float* __restrict__ Vb = g_V + (size_t)b * LQ * KC + n;
    __nv_bfloat16* __restrict__ Hn = g_VhiT + ((size_t)b * KC + n) * LQ;
    __nv_bfloat16* __restrict__ Ln = g_VloT + ((size_t)b * KC + n) * LQ;

    for (int j = threadIdx.x; j < pad; j += 256) {
        float v = 0.0f;
        if (j < cnt) {
            int l = __ldg(idxb + j);
            v = __ldg(Vb + (size_t)l * KC);
        }
        __nv_bfloat16 hi = __float2bfloat16(v);
        Hn[j] = hi;
        Ln[j] = __float2bfloat16(v - __bfloat162float(hi));
    }
}

// ===================================================================
// Kernel 3: score GEMM via bf16 mma.sync, merged 3-combo split.
// Per BK=16 chunk stage {Ahi, Alo, Bhi, Blo} once; issue hi.hi + hi.lo
// + lo.hi into the same accumulators. 128x128 tile, 8 warps (2x4),
// warp 64x32, 3-stage cp.async ring, sw32 swizzle. Block-triangle symm.
// ===================================================================
#define STILE 4096             // one operand tile: 128 rows x 32B
#define SBUF  (4 * STILE)      // 16KB per stage

__global__ void __launch_bounds__(256) gemm_s_mma_kernel(float* __restrict__ out)
{
    if (blockIdx.x < blockIdx.y) return;

    __shared__ __align__(16) unsigned char smem_raw[3 * SBUF];  // 48KB

    int t = threadIdx.x;
    int lane = t & 31;
    int wid = t >> 5;
    int warp_m = wid >> 2;       // 0..1
    int warp_n = wid & 3;        // 0..3
    int b = blockIdx.z;
    int p0 = blockIdx.y * 128;
    int q0 = blockIdx.x * 128;

    uint32_t sbase = smem_u32(smem_raw);
    const char* Abase = (const char*)g_Pbf + ((size_t)b * LQ + p0) * (KP * 2);
    const char* Bbase = (const char*)g_Pbf + ((size_t)b * LQ + q0) * (KP * 2);

    float acc[4][4][4];
#pragma unroll
    for (int i = 0; i < 4; i++)
#pragma unroll
        for (int j = 0; j < 4; j++)
#pragma unroll
            for (int k = 0; k < 4; k++) acc[i][j][k] = 0.0f;

    const int NIT = 36;     // 576 / 16
    // stage 4 tiles for chunk kc into buffer buf
    auto stage = [&](int buf, int kc) {
        uint32_t sdst = sbase + buf * SBUF;
        size_t col = (size_t)kc * 32;
#pragma unroll
        for (int r = 0; r < 4; r++) {
            int id = r * 256 + t;          // 0..1023
            int tile = id >> 8;            // 0=Ahi 1=Alo 2=Bhi 3=Blo
            int rid = id & 255;
            int row = rid >> 1, u = rid & 1;
            const char* src = (tile < 2 ? Abase : Bbase)
                            + (size_t)row * (KP * 2) + col
                            + ((tile & 1) ? 1152 : 0)
                            + u * 16;
            cp16(sdst + tile * STILE + sw32(row, u), src);
        }
    };

    int lr = lane & 7, sel = lane >> 3;
    auto compute = [&](int buf) {
        uint32_t sAhi = sbase + buf * SBUF;
        uint32_t sAlo = sAhi + STILE;
        uint32_t sBhi = sAhi + 2 * STILE;
        uint32_t sBlo = sAhi + 3 * STILE;

        uint32_t ah[4][4], al[4][4];
#pragma unroll
        for (int mt = 0; mt < 4; mt++) {
            int row = warp_m * 64 + mt * 16 + lr + (sel & 1) * 8;
            int cc = sel >> 1;
            ldsm4(sAhi + sw32(row, cc), ah[mt][0], ah[mt][1], ah[mt][2], ah[mt][3]);
            ldsm4(sAlo + sw32(row, cc), al[mt][0], al[mt][1], al[mt][2], al[mt][3]);
        }
        uint32_t bh[2][4], bl[2][4];
#pragma unroll
        for (int ntp = 0; ntp < 2; ntp++) {
            int row = warp_n * 32 + ntp * 16 + lr + (sel >> 1) * 8;
            int cc = sel & 1;
            ldsm4(sBhi + sw32(row, cc), bh[ntp][0], bh[ntp][1], bh[ntp][2], bh[ntp][3]);
            ldsm4(sBlo + sw32(row, cc), bl[ntp][0], bl[ntp][1], bl[ntp][2], bl[ntp][3]);
        }
#pragma unroll
        for (int mt = 0; mt < 4; mt++)
#pragma unroll
            for (int nt = 0; nt < 4; nt++) {
                int g = nt >> 1, h = (nt & 1) * 2;
                // hi.hi
                mma16816(acc[mt][nt][0], acc[mt][nt][1], acc[mt][nt][2], acc[mt][nt][3],
                         ah[mt][0], ah[mt][1], ah[mt][2], ah[mt][3], bh[g][h], bh[g][h + 1]);
                // hi.lo
                mma16816(acc[mt][nt][0], acc[mt][nt][1], acc[mt][nt][2], acc[mt][nt][3],
                         ah[mt][0], ah[mt][1], ah[mt][2], ah[mt][3], bl[g][h], bl[g][h + 1]);
                // lo.hi
                mma16816(acc[mt][nt][0], acc[mt][nt][1], acc[mt][nt][2], acc[mt][nt][3],
                         al[mt][0], al[mt][1], al[mt][2], al[mt][3], bh[g][h], bh[g][h + 1]);
            }
    };

    stage(0, 0);
    cp_commit();
    for (int it = 0; it < NIT; it++) {
        if (it + 1 < NIT) {
            stage((it + 1) % 3, it + 1);
            cp_commit();
            cp_wait<1>();
        } else {
            cp_wait<0>();
        }
        __syncthreads();
        compute(it % 3);
    }

    // ---- epilogue: two 64-row phases through SMEM; write both halves ----
    const float* __restrict__ inv = g_invden + b * LQ;
    float* __restrict__ Cb = out + YSZ + (size_t)b * LQ * LQ;
    float* S = (float*)smem_raw;   // 64 x 132 floats = 33792 B <= 48KB

#pragma unroll
    for (int mhalf = 0; mhalf < 2; mhalf++) {
        __syncthreads();
        if (warp_m == mhalf) {
            int r0l = lane >> 2;
            int c0l = (lane & 3) * 2;
#pragma unroll
            for (int mt = 0; mt < 4; mt++)
#pragma unroll
                for (int nt = 0; nt < 4; nt++) {
                    int rr = mt * 16 + r0l;
                    int cc = warp_n * 32 + nt * 8 + c0l;
                    S[rr * 132 + cc]           = acc[mt][nt][0];
                    S[rr * 132 + cc + 1]       = acc[mt][nt][1];
                    S[(rr + 8) * 132 + cc]     = acc[mt][nt][2];
                    S[(rr + 8) * 132 + cc + 1] = acc[mt][nt][3];
                }
        }
        __syncthreads();
        // normal half: att[p0+mhalf*64+r][q0+c] = dot * inv[q0+c]
        {
            int r = t >> 2, cs = (t & 3) * 32;
            float* dst = Cb + (size_t)(p0 + mhalf * 64 + r) * LQ + q0 + cs;
            const float* sp = S + r * 132 + cs;
#pragma unroll 8
            for (int j = 0; j < 32; j++)
                dst[j] = sp[j] * __ldg(inv + q0 + cs + j);
        }
        // mirrored half: att[q0+c][p0+mhalf*64+r] = dot * inv[p0+mhalf*64+r]
        {
            int c = t >> 1, rs = (t & 1) * 32;
            float* dst = Cb + (size_t)(q0 + c) * LQ + p0 + mhalf * 64 + rs;
#pragma unroll 8
            for (int i = 0; i < 32; i++)
                dst[i] = S[(rs + i) * 132 + c] * __ldg(inv + p0 + mhalf * 64 + rs + i);
        }
    }
}

// ===================================================================
// Kernel 4: fuse + stable softmax (active columns) -> split-bf16 U
// ===================================================================
__global__ void __launch_bounds__(256) fuse_softmax_kernel(const float* __restrict__ out)
{
    int b = blockIdx.y;
    int p = blockIdx.x;
    const float* __restrict__ ab = out + YSZ + (size_t)b * LQ * LQ;
    const int* __restrict__ idxb = g_idx + b * LQ;
    __nv_bfloat16* __restrict__ Uhp = g_Uhi + ((size_t)b * LQ + p) * LQ;
    __nv_bfloat16* __restrict__ Ulp = g_Ulo + ((size_t)b * LQ + p) * LQ;

    int cnt = g_cnt[b * 2 + 0];
    int pad = g_cnt[b * 2 + 1];

    int qi = p >> 6, qj = p & 63;
    int ap = (qj << 6) | qi;

    __shared__ float zbuf[LQ];
    __shared__ float red[256];

    int t = threadIdx.x;
    float lmax = (cnt < LQ) ? 0.0f : -3.4e38f;

    for (int j = t; j < pad; j += 256) {
        float z = 0.0f;
        if (j < cnt) {
            int l = __ldg(idxb + j);
            int ki = l >> 6, kj = l & 63;
            int bp = (kj << 6) | ki;
            float acc = 0.0f;
#pragma unroll
            for (int d2 = -1; d2 <= 1; d2++) {
                int aa = ap + d2;
                int bb = bp + d2;
                if ((unsigned)aa < LQ && (unsigned)bb < LQ) {
                    int u0 = ((aa & 63) << 6) | (aa >> 6);
                    int v0 = ((bb & 63) << 6) | (bb >> 6);
#pragma unroll
                    for (int d1 = -1; d1 <= 1; d1++) {
                        int uu = u0 + d1, vv = v0 + d1;
                        if ((unsigned)uu < LQ && (unsigned)vv < LQ)
                            acc += __ldg(ab + (size_t)uu * LQ + vv);
                    }
                }
            }
            z = acc * 10.0f;
            lmax = fmaxf(lmax, z);
        }
        zbuf[j] = z;
    }

    red[t] = lmax;
    __syncthreads();
    for (int off = 128; off >= 1; off >>= 1) {
        if (t < off) red[t] = fmaxf(red[t], red[t + off]);
        __syncthreads();
    }
    float rmax = red[0];
    __syncthreads();

    float lsum = 0.0f;
    for (int j = t; j < pad; j += 256) {
        float e = 0.0f;
        if (j < cnt) {
            e = expf(zbuf[j] - rmax);
            lsum += e;
        }
        zbuf[j] = e;
    }
    red[t] = lsum;
    __syncthreads();
    for (int off = 128; off >= 1; off >>= 1) {
        if (t < off) red[t] += red[t + off];
        __syncthreads();
    }
    float den = red[0] + (float)(LQ - cnt) * expf(-rmax);
    float invs = 1.0f / den;
    __syncthreads();

    for (int j = t; j < pad; j += 256) {
        float val = zbuf[j] * invs;
        __nv_bfloat16 hi = __float2bfloat16(val);
        Uhp[j] = hi;
        Ulp[j] = __float2bfloat16(val - __bfloat162float(hi));
    }
}

// ===================================================================
// Kernel 5: recon GEMM via bf16 mma.sync, merged 3-combo split.
// Z[p][n] = sum_j U[p][j] * VT[n][j]; K = pad (runtime, 64-aligned).
// 128x96 tile, 8 warps (2x4), warp 64x24, BK=16, 3-stage ring.
// ===================================================================
#define ZTA 4096   // U tile: 128 x 32B
#define ZTB 3072   // VT tile: 96 x 32B
#define ZBUF (2 * ZTA + 2 * ZTB)   // 14KB per stage

__global__ void __launch_bounds__(256) gemm_z_mma_kernel()
{
    __shared__ __align__(16) unsigned char smem_raw[3 * ZBUF];  // 42KB

    int t = threadIdx.x;
    int lane = t & 31;
    int wid = t >> 5;
    int warp_m = wid >> 2;       // 0..1
    int warp_n = wid & 3;        // 0..3
    int b = blockIdx.z;
    int p0 = blockIdx.y * 128;
    int n0 = blockIdx.x * 96;

    int kmax = g_cnt[b * 2 + 1];            // 64-aligned
    int NIT = kmax >> 4;                     // BK=16 chunks

    uint32_t sbase = smem_u32(smem_raw);
    const char* Ah = (const char*)(g_Uhi + ((size_t)b * LQ + p0) * LQ);
    const char* Al = (const char*)(g_Ulo + ((size_t)b * LQ + p0) * LQ);
    const char* Bh = (const char*)(g_VhiT + ((size_t)b * KC + n0) * LQ);
    const char* Bl = (const char*)(g_VloT + ((size_t)b * KC + n0) * LQ);

    float acc[4][3][4];
#pragma unroll
    for (int i = 0; i < 4; i++)
#pragma unroll
        for (int j = 0; j < 3; j++)
#pragma unroll
            for (int k = 0; k < 4; k++) acc[i][j][k] = 0.0f;

    auto stage = [&](int buf, int kc) {
        uint32_t sdst = sbase + buf * ZBUF;
        size_t col = (size_t)kc * 32;
        for (int i = t; i < 896; i += 256) {
            if (i < 512) {
                const char* src = (i < 256) ? Ah : Al;
                uint32_t base = sdst + ((i < 256) ? 0 : ZTA);
                int rid = i & 255;
                int row = rid >> 1, u = rid & 1;
                cp16(base + sw32(row, u), src + (size_t)row * (LQ * 2) + col + u * 16);
            } else {
                int j = i - 512;                 // 0..383
                const char* src = (j < 192) ? Bh : Bl;
                uint32_t base = sdst + 2 * ZTA + ((j < 192) ? 0 : ZTB);
                int rid = (j < 192) ? j : (j - 192);
                int row = rid >> 1, u = rid & 1;
                cp16(base + sw32(row, u), src + (size_t)row * (LQ * 2) + col + u * 16);
            }
        }
    };

    int lr = lane & 7, sel = lane >> 3;
    int half2 = (lane >> 3) & 1;
    auto compute = [&](int buf) {
        uint32_t sAh = sbase + buf * ZBUF;
        uint32_t sAl = sAh + ZTA;
        uint32_t sBh = sAh + 2 * ZTA;
        uint32_t sBl = sBh + ZTB;

        uint32_t ah[4][4], al[4][4];
#pragma unroll
        for (int mt = 0; mt < 4; mt++) {
            int row = warp_m * 64 + mt * 16 + lr + (sel & 1) * 8;
            int cc = sel >> 1;
            ldsm4(sAh + sw32(row, cc), ah[mt][0], ah[mt][1], ah[mt][2], ah[mt][3]);
            ldsm4(sAl + sw32(row, cc), al[mt][0], al[mt][1], al[mt][2], al[mt][3]);
        }
        uint32_t bh[6], bl[6];
        {
            int row = warp_n * 24 + lr + (sel >> 1) * 8;
            int cc = sel & 1;
            ldsm4(sBh + sw32(row, cc), bh[0], bh[1], bh[2], bh[3]);
            ldsm4(sBl + sw32(row, cc), bl[0], bl[1], bl[2], bl[3]);
        }
        {
            int row = warp_n * 24 + 16 + lr;
            int cc = half2;
            ldsm2(sBh + sw32(row, cc), bh[4], bh[5]);
            ldsm2(sBl + sw32(row, cc), bl[4], bl[5]);
        }
#pragma unroll
        for (int mt = 0; mt < 4; mt++)
#pragma unroll
            for (int nt = 0; nt < 3; nt++) {
                mma16816(acc[mt][nt][0], acc[mt][nt][1], acc[mt][nt][2], acc[mt][nt][3],
                         ah[mt][0], ah[mt][1], ah[mt][2], ah[mt][3], bh[nt * 2], bh[nt * 2 + 1]);
                mma16816(acc[mt][nt][0], acc[mt][nt][1], acc[mt][nt][2], acc[mt][nt][3],
                         ah[mt][0], ah[mt][1], ah[mt][2], ah[mt][3], bl[nt * 2], bl[nt * 2 + 1]);
                mma16816(acc[mt][nt][0], acc[mt][nt][1], acc[mt][nt][2], acc[mt][nt][3],
                         al[mt][0], al[mt][1], al[mt][2], al[mt][3], bh[nt * 2], bh[nt * 2 + 1]);
            }
    };

    stage(0, 0);
    cp_commit();
    for (int it = 0; it < NIT; it++) {
        if (it + 1 < NIT) {
            stage((it + 1) % 3, it + 1);
            cp_commit();
            cp_wait<1>();
        } else {
            cp_wait<0>();
        }
        __syncthreads();
        compute(it % 3);
    }

    // epilogue: direct float2 stores to g_Z
    float* __restrict__ Zb = g_Z + (size_t)b * LQ * KC;
    int r0l = lane >> 2;
    int c0l = (lane & 3) * 2;
#pragma unroll
    for (int mt = 0; mt < 4; mt++)
#pragma unroll
        for (int nt = 0; nt < 3; nt++) {
            int row = p0 + warp_m * 64 + mt * 16 + r0l;
            int col = n0 + warp_n * 24 + nt * 8 + c0l;
            *(float2*)(Zb + (size_t)row * KC + col) =
                make_float2(acc[mt][nt][0], acc[mt][nt][1]);
            *(float2*)(Zb + (size_t)(row + 8) * KC + col) =
                make_float2(acc[mt][nt][2], acc[mt][nt][3]);
        }
}

// ===================================================================
// Kernel 6: overlap-add (transposed conv gather)
// ===================================================================
__global__ void recon_kernel(float* __restrict__ out)
{
    int idx = blockIdx.x * blockDim.x + threadIdx.x;
    if (idx >= (int)YSZ) return;
    int c = idx & 63;
    int tmp = idx >> 6;
    int J = tmp & 127; tmp >>= 7;
    int I = tmp & 127;
    int b = tmp >> 7;

    int ri[2], rdh[2], rn = 0;
    if (I & 1) { ri[0] = (I - 1) >> 1; rdh[0] = 1; rn = 1; }
    else {
        ri[rn] = I >> 1; rdh[rn] = 0; rn++;
        if (I >= 2) { ri[rn] = (I >> 1) - 1; rdh[rn] = 2; rn++; }
    }
    int cj[2], cdw[2], cn = 0;
    if (J & 1) { cj[0] = (J - 1) >> 1; cdw[0] = 1; cn = 1; }
    else {
        cj[cn] = J >> 1; cdw[cn] = 0; cn++;
        if (J >= 2) { cj[cn] = (J >> 1) - 1; cdw[cn] = 2; cn++; }
    }

    const float* __restrict__ Zb = g_Z + (size_t)b * LQ * KC;
    float acc = 0.0f;
    for (int a = 0; a < rn; a++) {
        for (int bb = 0; bb < cn; bb++) {
            int l = ri[a] * 64 + cj[bb];
            int n = (rdh[a] * 3 + cdw[bb]) * 64 + c;
            acc += Zb[(size_t)l * KC + n];
        }
    }
    out[idx] = 0.25f * acc;
}

// ===================================================================
extern "C" void kernel_launch(void* const* d_in, const int* in_sizes, int n_in,
                              void* d_out, int out_size)
{
    const float* x    = (const float*)d_in[0];
    const float* mask = (const float*)d_in[1];
    float* out = (float*)d_out;
    (void)in_sizes; (void)n_in; (void)out_size;

    build_pv_kernel<<<dim3(LQ, BATCH), 576>>>(x);
    mm_kernel<<<(BATCH * LQ + 255) / 256, 256>>>(mask);
    compact_kernel<<<BATCH, 1024>>>();
    vcompT_kernel<<<dim3(KC, BATCH), 256>>>();
    gemm_s_mma_kernel<<<dim3(32, 32, BATCH), 256>>>(out);
    fuse_softmax_kernel<<<dim3(LQ, BATCH), 256>>>(out);
    gemm_z_mma_kernel<<<dim3(6, 32, BATCH), 256>>>();
    recon_kernel<<<(int)((YSZ + 255) / 256), 256>>>(out);
}

// round 8
// speedup vs baseline: 4.2578x; 1.0765x over previous
#include <cuda_runtime.h>
#include <cuda_bf16.h>
#include <cuda_fp16.h>
#include <cstdint>

// Problem constants
#define BATCH 2
#define HFULL 128
#define WFULL 128
#define CCH   64
#define HLO   64
#define WLO   64
#define LQ    4096          // HLO*WLO
#define KC    576           // 3*3*CCH
#define KP    1152          // split width: [hi(576) | lo(576)]

static const size_t YSZ = (size_t)BATCH * HFULL * WFULL * CCH; // y output floats

// -------- static device scratch --------
__device__ __align__(16) __nv_bfloat16 g_Pbf[(size_t)BATCH * LQ * KP];  // [hi|lo] per row
__device__ float g_Z[(size_t)BATCH * LQ * KC];
__device__ __align__(16) __half g_Uhi[(size_t)BATCH * LQ * LQ];
__device__ __align__(16) __half g_Ulo[(size_t)BATCH * LQ * LQ];
__device__ __align__(16) __half g_VT[(size_t)BATCH * KC * LQ];  // [n][j] fp16-quantized
__device__ float g_invden[BATCH * LQ];
__device__ float g_mm[BATCH * LQ];
__device__ int   g_idx[BATCH * LQ];
__device__ int   g_cnt[BATCH * 2];

// ---------------- helpers (baseline sm_80-era PTX, safe on compute_103) ----
__device__ __forceinline__ uint32_t smem_u32(const void* p) {
    uint32_t a;
    asm("{ .reg .u64 t; cvta.to.shared.u64 t, %1; cvt.u32.u64 %0, t; }" : "=r"(a) : "l"(p));
    return a;
}
__device__ __forceinline__ void cp16(uint32_t dst, const void* src) {
    asm volatile("cp.async.cg.shared.global [%0], [%1], 16;" :: "r"(dst), "l"(src));
}
__device__ __forceinline__ void cp_commit() {
    asm volatile("cp.async.commit_group;");
}
template<int N> __device__ __forceinline__ void cp_wait() {
    asm volatile("cp.async.wait_group %0;" :: "n"(N));
}
__device__ __forceinline__ void ldsm4(uint32_t a, uint32_t& r0, uint32_t& r1, uint32_t& r2, uint32_t& r3) {
    asm volatile("ldmatrix.sync.aligned.m8n8.x4.shared.b16 {%0,%1,%2,%3}, [%4];"
                 : "=r"(r0), "=r"(r1), "=r"(r2), "=r"(r3) : "r"(a));
}
__device__ __forceinline__ void ldsm2(uint32_t a, uint32_t& r0, uint32_t& r1) {
    asm volatile("ldmatrix.sync.aligned.m8n8.x2.shared.b16 {%0,%1}, [%2];"
                 : "=r"(r0), "=r"(r1) : "r"(a));
}
__device__ __forceinline__ void mma16816(float& c0, float& c1, float& c2, float& c3,
                                         uint32_t a0, uint32_t a1, uint32_t a2, uint32_t a3,
                                         uint32_t b0, uint32_t b1) {
    asm volatile("mma.sync.aligned.m16n8k16.row.col.f32.bf16.bf16.f32 "
                 "{%0,%1,%2,%3}, {%4,%5,%6,%7}, {%8,%9}, {%0,%1,%2,%3};"
                 : "+f"(c0), "+f"(c1), "+f"(c2), "+f"(c3)
                 : "r"(a0), "r"(a1), "r"(a2), "r"(a3), "r"(b0), "r"(b1));
}
__device__ __forceinline__ void mma16816h(float& c0, float& c1, float& c2, float& c3,
                                          uint32_t a0, uint32_t a1, uint32_t a2, uint32_t a3,
                                          uint32_t b0, uint32_t b1) {
    asm volatile("mma.sync.aligned.m16n8k16.row.col.f32.f16.f16.f32 "
                 "{%0,%1,%2,%3}, {%4,%5,%6,%7}, {%8,%9}, {%0,%1,%2,%3};"
                 : "+f"(c0), "+f"(c1), "+f"(c2), "+f"(c3)
                 : "r"(a0), "r"(a1), "r"(a2), "r"(a3), "r"(b0), "r"(b1));
}

// XOR-swizzled smem offset for 32B rows (BK=16), 16B chunks
__device__ __forceinline__ uint32_t sw32(int row, int chunk) {
    return (uint32_t)(row * 32 + 16 * (chunk ^ ((row >> 2) & 1)));
}

// ===================================================================
// Kernel 1: build split-bf16 P + invden
// ===================================================================
__global__ void __launch_bounds__(576) build_pv_kernel(const float* __restrict__ x)
{
    int b = blockIdx.y;
    int l = blockIdx.x;
    int li = l >> 6, lj = l & 63;
    int t = threadIdx.x;
    int c = t & 63;
    int g = t >> 6;
    int dh = g / 3, dw = g % 3;

    const size_t xb = (size_t)b * HFULL * WFULL * CCH;

    int fi = li - 1 + dh;
    int fj = lj - 1 + dw;
    float pv = 0.0f;
    if (fi >= 0 && fi < HLO && fj >= 0 && fj < WLO) {
        size_t base = xb + (size_t)(2 * fi) * (WFULL * CCH) + (size_t)(2 * fj) * CCH + c;
        pv = 0.25f * (x[base] + x[base + CCH] + x[base + WFULL * CCH] + x[base + WFULL * CCH + CCH]);
    }
    __nv_bfloat16 hi = __float2bfloat16(pv);
    float lof = pv - __bfloat162float(hi);
    __nv_bfloat16 lo = __float2bfloat16(lof);
    size_t rb = ((size_t)b * LQ + l) * KP;
    g_Pbf[rb + t] = hi;
    g_Pbf[rb + KC + t] = lo;

    // norm reduce: warp shuffles + tiny cross-warp
    float sq = pv * pv;
#pragma unroll
    for (int off = 16; off >= 1; off >>= 1)
        sq += __shfl_xor_sync(0xffffffffu, sq, off);
    __shared__ float ws[18];
    int warp = t >> 5, lane = t & 31;
    if (lane == 0) ws[warp] = sq;
    __syncthreads();
    if (t == 0) {
        float s = 0.0f;
#pragma unroll
        for (int w = 0; w < 18; w++) s += ws[w];
        g_invden[b * LQ + l] = 1.0f / fmaxf(sqrtf(s), 1e-4f);
    }
}

// ===================================================================
// Kernel 2: mask gate
// ===================================================================
__global__ void mm_kernel(const float* __restrict__ mask)
{
    int idx = blockIdx.x * blockDim.x + threadIdx.x;
    if (idx >= BATCH * LQ) return;
    int b = idx / LQ;
    int l = idx % LQ;
    int li = l >> 6, lj = l & 63;
    const size_t mb = (size_t)b * HFULL * WFULL;

    float sum9 = 0.0f;
    for (int dh = 0; dh < 3; dh++) {
        for (int dw = 0; dw < 3; dw++) {
            int fi = li - 1 + dh, fj = lj - 1 + dw;
            if (fi >= 0 && fi < HLO && fj >= 0 && fj < WLO) {
                size_t base = mb + (size_t)(2 * fi) * WFULL + (2 * fj);
                sum9 += 0.25f * (mask[base] + mask[base + 1] + mask[base + WFULL] + mask[base + WFULL + 1]);
            }
        }
    }
    float mean = sum9 / 9.0f;
    g_mm[idx] = (mean == 1.0f) ? 1.0f : 0.0f;
}

// ===================================================================
// Kernel 2b: deterministic compaction of active columns (pad to 64)
// ===================================================================
__global__ void __launch_bounds__(1024) compact_kernel()
{
    int b = blockIdx.x;
    int t = threadIdx.x;
    __shared__ int sc[1024];

    int base = t * 4;
    int loc[4];
    int cnt = 0;
#pragma unroll
    for (int i = 0; i < 4; i++) {
        loc[i] = (g_mm[b * LQ + base + i] != 0.0f) ? 1 : 0;
        cnt += loc[i];
    }
    sc[t] = cnt;
    __syncthreads();
    for (int off = 1; off < 1024; off <<= 1) {
        int v = (t >= off) ? sc[t - off] : 0;
        __syncthreads();
        sc[t] += v;
        __syncthreads();
    }
    int pos = sc[t] - cnt;
#pragma unroll
    for (int i = 0; i < 4; i++) {
        if (loc[i]) g_idx[b * LQ + (pos++)] = base + i;
    }
    if (t == 1023) {
        int total = sc[1023];
        int pad = (total + 63) & ~63;
        g_cnt[b * 2 + 0] = total;
        g_cnt[b * 2 + 1] = pad;
        for (int j = total; j < pad; j++) g_idx[b * LQ + j] = 0;
    }
}

// ===================================================================
// Kernel 2c: compacted-transposed fp16 V read straight from x:
// VT[n][j] = x[2*li+dh][2*lj+dw][c], n=(dh*3+dw)*64+c, l=idx[j]
// ===================================================================
__global__ void __launch_bounds__(256) vcompT_kernel(const float* __restrict__ x)
{
    int b = blockIdx.y;
    int n = blockIdx.x;
    int g = n >> 6;
    int c = n & 63;
    int dh = g / 3, dw = g % 3;
    int cnt = g_cnt[b * 2 + 0];
    int pad = g_cnt[b * 2 + 1];
    const int* __restrict__ idxb = g_idx + b * LQ;
    const float* __restrict__ xb = x + (size_t)b * HFULL * WFULL * CCH;
    __half* __restrict__ Vn = g_VT + ((size_t)b * KC + n) * LQ;

    for (int j = threadIdx.x; j < pad; j += 256) {
        float v = 0.0f;
        if (j < cnt) {
            int l = __ldg(idxb + j);
            int xr = 2 * (l >> 6) + dh;
            int xc = 2 * (l & 63) + dw;
            if (xr < HFULL && xc < WFULL)
                v = __ldg(xb + (size_t)xr * (WFULL * CCH) + (size_t)xc * CCH + c);
        }
        Vn[j] = __float2half(v);
    }
}

// ===================================================================
// Kernel 3: score GEMM via bf16 mma.sync, merged 3-combo split.
// 128x128 tile, 8 warps (2x4), warp 64x32, BK=16, 3-stage ring.
// Block-triangle symmetric.
// ===================================================================
#define STILE 4096             // one operand tile: 128 rows x 32B
#define SBUF  (4 * STILE)      // 16KB per stage

__global__ void __launch_bounds__(256) gemm_s_mma_kernel(float* __restrict__ out)
{
    if (blockIdx.x < blockIdx.y) return;

    __shared__ __align__(16) unsigned char smem_raw[3 * SBUF];  // 48KB

    int t = threadIdx.x;
    int lane = t & 31;
    int wid = t >> 5;
    int warp_m = wid >> 2;       // 0..1
    int warp_n = wid & 3;        // 0..3
    int b = blockIdx.z;
    int p0 = blockIdx.y * 128;
    int q0 = blockIdx.x * 128;

    uint32_t sbase = smem_u32(smem_raw);
    const char* Abase = (const char*)g_Pbf + ((size_t)b * LQ + p0) * (KP * 2);
    const char* Bbase = (const char*)g_Pbf + ((size_t)b * LQ + q0) * (KP * 2);

    float acc[4][4][4];
#pragma unroll
    for (int i = 0; i < 4; i++)
#pragma unroll
        for (int j = 0; j < 4; j++)
#pragma unroll
            for (int k = 0; k < 4; k++) acc[i][j][k] = 0.0f;

    const int NIT = 36;     // 576 / 16
    auto stage = [&](int buf, int kc) {
        uint32_t sdst = sbase + buf * SBUF;
        size_t col = (size_t)kc * 32;
#pragma unroll
        for (int r = 0; r < 4; r++) {
            int id = r * 256 + t;          // 0..1023
            int tile = id >> 8;            // 0=Ahi 1=Alo 2=Bhi 3=Blo
            int rid = id & 255;
            int row = rid >> 1, u = rid & 1;
            const char* src = (tile < 2 ? Abase : Bbase)
                            + (size_t)row * (KP * 2) + col
                            + ((tile & 1) ? 1152 : 0)
                            + u * 16;
            cp16(sdst + tile * STILE + sw32(row, u), src);
        }
    };

    int lr = lane & 7, sel = lane >> 3;
    auto compute = [&](int buf) {
        uint32_t sAhi = sbase + buf * SBUF;
        uint32_t sAlo = sAhi + STILE;
        uint32_t sBhi = sAhi + 2 * STILE;
        uint32_t sBlo = sAhi + 3 * STILE;

        uint32_t ah[4][4], al[4][4];
#pragma unroll
        for (int mt = 0; mt < 4; mt++) {
            int row = warp_m * 64 + mt * 16 + lr + (sel & 1) * 8;
            int cc = sel >> 1;
            ldsm4(sAhi + sw32(row, cc), ah[mt][0], ah[mt][1], ah[mt][2], ah[mt][3]);
            ldsm4(sAlo + sw32(row, cc), al[mt][0], al[mt][1], al[mt][2], al[mt][3]);
        }
        uint32_t bh[2][4], bl[2][4];
#pragma unroll
        for (int ntp = 0; ntp < 2; ntp++) {
            int row = warp_n * 32 + ntp * 16 + lr + (sel >> 1) * 8;
            int cc = sel & 1;
            ldsm4(sBhi + sw32(row, cc), bh[ntp][0], bh[ntp][1], bh[ntp][2], bh[ntp][3]);
            ldsm4(sBlo + sw32(row, cc), bl[ntp][0], bl[ntp][1], bl[ntp][2], bl[ntp][3]);
        }
#pragma unroll
        for (int mt = 0; mt < 4; mt++)
#pragma unroll
            for (int nt = 0; nt < 4; nt++) {
                int g = nt >> 1, h = (nt & 1) * 2;
                mma16816(acc[mt][nt][0], acc[mt][nt][1], acc[mt][nt][2], acc[mt][nt][3],
                         ah[mt][0], ah[mt][1], ah[mt][2], ah[mt][3], bh[g][h], bh[g][h + 1]);
                mma16816(acc[mt][nt][0], acc[mt][nt][1], acc[mt][nt][2], acc[mt][nt][3],
                         ah[mt][0], ah[mt][1], ah[mt][2], ah[mt][3], bl[g][h], bl[g][h + 1]);
                mma16816(acc[mt][nt][0], acc[mt][nt][1], acc[mt][nt][2], acc[mt][nt][3],
                         al[mt][0], al[mt][1], al[mt][2], al[mt][3], bh[g][h], bh[g][h + 1]);
            }
    };

    stage(0, 0);
    cp_commit();
    for (int it = 0; it < NIT; it++) {
        if (it + 1 < NIT) {
            stage((it + 1) % 3, it + 1);
            cp_commit();
            cp_wait<1>();
        } else {
            cp_wait<0>();
        }
        __syncthreads();
        compute(it % 3);
    }

    // ---- epilogue: two 64-row phases through SMEM; write both halves ----
    const float* __restrict__ inv = g_invden + b * LQ;
    float* __restrict__ Cb = out + YSZ + (size_t)b * LQ * LQ;
    float* S = (float*)smem_raw;   // 64 x 132 floats

#pragma unroll
    for (int mhalf = 0; mhalf < 2; mhalf++) {
        __syncthreads();
        if (warp_m == mhalf) {
            int r0l = lane >> 2;
            int c0l = (lane & 3) * 2;
#pragma unroll
            for (int mt = 0; mt < 4; mt++)
#pragma unroll
                for (int nt = 0; nt < 4; nt++) {
                    int rr = mt * 16 + r0l;
                    int cc = warp_n * 32 + nt * 8 + c0l;
                    S[rr * 132 + cc]           = acc[mt][nt][0];
                    S[rr * 132 + cc + 1]       = acc[mt][nt][1];
                    S[(rr + 8) * 132 + cc]     = acc[mt][nt][2];
                    S[(rr + 8) * 132 + cc + 1] = acc[mt][nt][3];
                }
        }
        __syncthreads();
        {
            int r = t >> 2, cs = (t & 3) * 32;
            float* dst = Cb + (size_t)(p0 + mhalf * 64 + r) * LQ + q0 + cs;
            const float* sp = S + r * 132 + cs;
#pragma unroll 8
            for (int j = 0; j < 32; j++)
                dst[j] = sp[j] * __ldg(inv + q0 + cs + j);
        }
        {
            int c = t >> 1, rs = (t & 1) * 32;
            float* dst = Cb + (size_t)(q0 + c) * LQ + p0 + mhalf * 64 + rs;
#pragma unroll 8
            for (int i = 0; i < 32; i++)
                dst[i] = S[(rs + i) * 132 + c] * __ldg(inv + p0 + mhalf * 64 + rs + i);
        }
    }
}

// ===================================================================
// Kernel 4: fuse + stable softmax -> split-fp16 U.
// 4 p per block (consecutive ap => shared gather rows stay L1-hot).
// ===================================================================
__global__ void __launch_bounds__(256) fuse_softmax_kernel(const float* __restrict__ out)
{
    int b = blockIdx.y;
    int bx = blockIdx.x;
    int qj = bx & 63;
    int qi0 = (bx >> 6) << 2;

    const float* __restrict__ ab = out + YSZ + (size_t)b * LQ * LQ;
    const int* __restrict__ idxb = g_idx + b * LQ;

    int cnt = g_cnt[b * 2 + 0];
    int pad = g_cnt[b * 2 + 1];

    __shared__ float zbuf[LQ];
    __shared__ float red[256];

    int t = threadIdx.x;

    for (int sub = 0; sub < 4; sub++) {
        int qi = qi0 + sub;
        int p = (qi << 6) | qj;
        int ap = (qj << 6) | qi;
        __half* __restrict__ Uhp = g_Uhi + ((size_t)b * LQ + p) * LQ;
        __half* __restrict__ Ulp = g_Ulo + ((size_t)b * LQ + p) * LQ;

        float lmax = (cnt < LQ) ? 0.0f : -3.4e38f;

        for (int j = t; j < pad; j += 256) {
            float z = 0.0f;
            if (j < cnt) {
                int l = __ldg(idxb + j);
                int ki = l >> 6, kj = l & 63;
                int bp = (kj << 6) | ki;
                float acc = 0.0f;
#pragma unroll
                for (int d2 = -1; d2 <= 1; d2++) {
                    int aa = ap + d2;
                    int bb = bp + d2;
                    if ((unsigned)aa < LQ && (unsigned)bb < LQ) {
                        int u0 = ((aa & 63) << 6) | (aa >> 6);
                        int v0 = ((bb & 63) << 6) | (bb >> 6);
#pragma unroll
                        for (int d1 = -1; d1 <= 1; d1++) {
                            int uu = u0 + d1, vv = v0 + d1;
                            if ((unsigned)uu < LQ && (unsigned)vv < LQ)
                                acc += __ldg(ab + (size_t)uu * LQ + vv);
                        }
                    }
                }
                z = acc * 10.0f;
                lmax = fmaxf(lmax, z);
            }
            zbuf[j] = z;
        }

        red[t] = lmax;
        __syncthreads();
        for (int off = 128; off >= 1; off >>= 1) {
            if (t < off) red[t] = fmaxf(red[t], red[t + off]);
            __syncthreads();
        }
        float rmax = red[0];
        __syncthreads();

        float lsum = 0.0f;
        for (int j = t; j < pad; j += 256) {
            float e = 0.0f;
            if (j < cnt) {
                e = expf(zbuf[j] - rmax);
                lsum += e;
            }
            zbuf[j] = e;
        }
        red[t] = lsum;
        __syncthreads();
        for (int off = 128; off >= 1; off >>= 1) {
            if (t < off) red[t] += red[t + off];
            __syncthreads();
        }
        float den = red[0] + (float)(LQ - cnt) * expf(-rmax);
        float invs = 1.0f / den;
        __syncthreads();

        for (int j = t; j < pad; j += 256) {
            float val = zbuf[j] * invs;
            __half hi = __float2half(val);
            Uhp[j] = hi;
            Ulp[j] = __float2half(val - __half2float(hi));
        }
        __syncthreads();
    }
}

// ===================================================================
// Kernel 5: recon GEMM via fp16 mma.sync, 2-combo:
// Z = (Uhi + Ulo) @ fp16(V)^T  == exact-U x fp16-quantized V.
// 128x96 tile, 8 warps (2x4), warp 64x24, BK=16, 3-stage ring.
// ===================================================================
#define ZTA 4096   // U tile: 128 x 32B
#define ZTB 3072   // VT tile: 96 x 32B
#define ZBUF (2 * ZTA + ZTB)   // 11KB per stage

__global__ void __launch_bounds__(256) gemm_z_mma_kernel()
{
    __shared__ __align__(16) unsigned char smem_raw[3 * ZBUF];  // 33KB

    int t = threadIdx.x;
    int lane = t & 31;
    int wid = t >> 5;
    int warp_m = wid >> 2;       // 0..1
    int warp_n = wid & 3;        // 0..3
    int b = blockIdx.z;
    int p0 = blockIdx.y * 128;
    int n0 = blockIdx.x * 96;

    int kmax = g_cnt[b * 2 + 1];            // 64-aligned
    int NIT = kmax >> 4;                     // BK=16 chunks

    uint32_t sbase = smem_u32(smem_raw);
    const char* Ah = (const char*)(g_Uhi + ((size_t)b * LQ + p0) * LQ);
    const char* Al = (const char*)(g_Ulo + ((size_t)b * LQ + p0) * LQ);
    const char* Bh = (const char*)(g_VT + ((size_t)b * KC + n0) * LQ);

    float acc[4][3][4];
#pragma unroll
    for (int i = 0; i < 4; i++)
#pragma unroll
        for (int j = 0; j < 3; j++)
#pragma unroll
            for (int k = 0; k < 4; k++) acc[i][j][k] = 0.0f;

    auto stage = [&](int buf, int kc) {
        uint32_t sdst = sbase + buf * ZBUF;
        size_t col = (size_t)kc * 32;
        for (int i = t; i < 704; i += 256) {
            if (i < 512) {
                const char* src = (i < 256) ? Ah : Al;
                uint32_t base = sdst + ((i < 256) ? 0 : ZTA);
                int rid = i & 255;
                int row = rid >> 1, u = rid & 1;
                cp16(base + sw32(row, u), src + (size_t)row * (LQ * 2) + col + u * 16);
            } else {
                int j = i - 512;                 // 0..191
                int row = j >> 1, u = j & 1;
                cp16(sdst + 2 * ZTA + sw32(row, u), Bh + (size_t)row * (LQ * 2) + col + u * 16);
            }
        }
    };

    int lr = lane & 7, sel = lane >> 3;
    int half2 = (lane >> 3) & 1;
    auto compute = [&](int buf) {
        uint32_t sAh = sbase + buf * ZBUF;
        uint32_t sAl = sAh + ZTA;
        uint32_t sBh = sAh + 2 * ZTA;

        uint32_t ah[4][4], al[4][4];
#pragma unroll
        for (int mt = 0; mt < 4; mt++) {
            int row = warp_m * 64 + mt * 16 + lr + (sel & 1) * 8;
            int cc = sel >> 1;
            ldsm4(sAh + sw32(row, cc), ah[mt][0], ah[mt][1], ah[mt][2], ah[mt][3]);
            ldsm4(sAl + sw32(row, cc), al[mt][0], al[mt][1], al[mt][2], al[mt][3]);
        }
        uint32_t bh[6];
        {
            int row = warp_n * 24 + lr + (sel >> 1) * 8;
            int cc = sel & 1;
            ldsm4(sBh + sw32(row, cc), bh[0], bh[1], bh[2], bh[3]);
        }
        {
            int row = warp_n * 24 + 16 + lr;
            int cc = half2;
            ldsm2(sBh + sw32(row, cc), bh[4], bh[5]);
        }
#pragma unroll
        for (int mt = 0; mt < 4; mt++)
#pragma unroll
            for (int nt = 0; nt < 3; nt++) {
                mma16816h(acc[mt][nt][0], acc[mt][nt][1], acc[mt][nt][2], acc[mt][nt][3],
                          ah[mt][0], ah[mt][1], ah[mt][2], ah[mt][3], bh[nt * 2], bh[nt * 2 + 1]);
                mma16816h(acc[mt][nt][0], acc[mt][nt][1], acc[mt][nt][2], acc[mt][nt][3],
                          al[mt][0], al[mt][1], al[mt][2], al[mt][3], bh[nt * 2], bh[nt * 2 + 1]);
            }
    };

    stage(0, 0);
    cp_commit();
    for (int it = 0; it < NIT; it++) {
        if (it + 1 < NIT) {
            stage((it + 1) % 3, it + 1);
            cp_commit();
            cp_wait<1>();
        } else {
            cp_wait<0>();
        }
        __syncthreads();
        compute(it % 3);
    }

    // epilogue: direct float2 stores to g_Z
    float* __restrict__ Zb = g_Z + (size_t)b * LQ * KC;
    int r0l = lane >> 2;
    int c0l = (lane & 3) * 2;
#pragma unroll
    for (int mt = 0; mt < 4; mt++)
#pragma unroll
        for (int nt = 0; nt < 3; nt++) {
            int row = p0 + warp_m * 64 + mt * 16 + r0l;
            int col = n0 + warp_n * 24 + nt * 8 + c0l;
            *(float2*)(Zb + (size_t)row * KC + col) =
                make_float2(acc[mt][nt][0], acc[mt][nt][1]);
            *(float2*)(Zb + (size_t)(row + 8) * KC + col) =
                make_float2(acc[mt][nt][2], acc[mt][nt][3]);
        }
}

// ===================================================================
// Kernel 6: overlap-add (transposed conv gather)
// ===================================================================
__global__ void recon_kernel(float* __restrict__ out)
{
    int idx = blockIdx.x * blockDim.x + threadIdx.x;
    if (idx >= (int)YSZ) return;
    int c = idx & 63;
    int tmp = idx >> 6;
    int J = tmp & 127; tmp >>= 7;
    int I = tmp & 127;
    int b = tmp >> 7;

    int ri[2], rdh[2], rn = 0;
    if (I & 1) { ri[0] = (I - 1) >> 1; rdh[0] = 1; rn = 1; }
    else {
        ri[rn] = I >> 1; rdh[rn] = 0; rn++;
        if (I >= 2) { ri[rn] = (I >> 1) - 1; rdh[rn] = 2; rn++; }
    }
    int cj[2], cdw[2], cn = 0;
    if (J & 1) { cj[0] = (J - 1) >> 1; cdw[0] = 1; cn = 1; }
    else {
        cj[cn] = J >> 1; cdw[cn] = 0; cn++;
        if (J >= 2) { cj[cn] = (J >> 1) - 1; cdw[cn] = 2; cn++; }
    }

    const float* __restrict__ Zb = g_Z + (size_t)b * LQ * KC;
    float acc = 0.0f;
    for (int a = 0; a < rn; a++) {
        for (int bb = 0; bb < cn; bb++) {
            int l = ri[a] * 64 + cj[bb];
            int n = (rdh[a] * 3 + cdw[bb]) * 64 + c;
            acc += Zb[(size_t)l * KC + n];
        }
    }
    out[idx] = 0.25f * acc;
}

// ===================================================================
extern "C" void kernel_launch(void* const* d_in, const int* in_sizes, int n_in,
                              void* d_out, int out_size)
{
    const float* x    = (const float*)d_in[0];
    const float* mask = (const float*)d_in[1];
    float* out = (float*)d_out;
    (void)in_sizes; (void)n_in; (void)out_size;

    build_pv_kernel<<<dim3(LQ, BATCH), 576>>>(x);
    mm_kernel<<<(BATCH * LQ + 255) / 256, 256>>>(mask);
    compact_kernel<<<BATCH, 1024>>>();
    vcompT_kernel<<<dim3(KC, BATCH), 256>>>(x);
    gemm_s_mma_kernel<<<dim3(32, 32, BATCH), 256>>>(out);
    fuse_softmax_kernel<<<dim3(1024, BATCH), 256>>>(out);
    gemm_z_mma_kernel<<<dim3(6, 32, BATCH), 256>>>();
    recon_kernel<<<(int)((YSZ + 255) / 256), 256>>>(out);
}

// round 9
// speedup vs baseline: 4.7320x; 1.1114x over previous
#include <cuda_runtime.h>
#include <cuda_fp16.h>
#include <cstdint>

// Problem constants
#define BATCH 2
#define HFULL 128
#define WFULL 128
#define CCH   64
#define HLO   64
#define WLO   64
#define LQ    4096          // HLO*WLO
#define KC    576           // 3*3*CCH
#define KP    1152          // split width: [hi(576) | lo(576)]

static const size_t YSZ = (size_t)BATCH * HFULL * WFULL * CCH; // y output floats

// -------- static device scratch --------
__device__ __align__(16) __half g_Phf[(size_t)BATCH * LQ * KP];  // fp16 [hi|lo] per row
__device__ float g_Z[(size_t)BATCH * LQ * KC];
__device__ __align__(16) __half g_Uhi[(size_t)BATCH * LQ * LQ];
__device__ __align__(16) __half g_Ulo[(size_t)BATCH * LQ * LQ];
__device__ __align__(16) __half g_VT[(size_t)BATCH * KC * LQ];  // [n][j] fp16-quantized
__device__ float g_invden[BATCH * LQ];
__device__ float g_mm[BATCH * LQ];
__device__ int   g_idx[BATCH * LQ];
__device__ int   g_cnt[BATCH * 2];

// ---------------- helpers (baseline sm_80-era PTX, safe on compute_103) ----
__device__ __forceinline__ uint32_t smem_u32(const void* p) {
    uint32_t a;
    asm("{ .reg .u64 t; cvta.to.shared.u64 t, %1; cvt.u32.u64 %0, t; }" : "=r"(a) : "l"(p));
    return a;
}
__device__ __forceinline__ void cp16(uint32_t dst, const void* src) {
    asm volatile("cp.async.cg.shared.global [%0], [%1], 16;" :: "r"(dst), "l"(src));
}
__device__ __forceinline__ void cp_commit() {
    asm volatile("cp.async.commit_group;");
}
template<int N> __device__ __forceinline__ void cp_wait() {
    asm volatile("cp.async.wait_group %0;" :: "n"(N));
}
__device__ __forceinline__ void ldsm4(uint32_t a, uint32_t& r0, uint32_t& r1, uint32_t& r2, uint32_t& r3) {
    asm volatile("ldmatrix.sync.aligned.m8n8.x4.shared.b16 {%0,%1,%2,%3}, [%4];"
                 : "=r"(r0), "=r"(r1), "=r"(r2), "=r"(r3) : "r"(a));
}
__device__ __forceinline__ void ldsm2(uint32_t a, uint32_t& r0, uint32_t& r1) {
    asm volatile("ldmatrix.sync.aligned.m8n8.x2.shared.b16 {%0,%1}, [%2];"
                 : "=r"(r0), "=r"(r1) : "r"(a));
}
__device__ __forceinline__ void mma16816h(float& c0, float& c1, float& c2, float& c3,
                                          uint32_t a0, uint32_t a1, uint32_t a2, uint32_t a3,
                                          uint32_t b0, uint32_t b1) {
    asm volatile("mma.sync.aligned.m16n8k16.row.col.f32.f16.f16.f32 "
                 "{%0,%1,%2,%3}, {%4,%5,%6,%7}, {%8,%9}, {%0,%1,%2,%3};"
                 : "+f"(c0), "+f"(c1), "+f"(c2), "+f"(c3)
                 : "r"(a0), "r"(a1), "r"(a2), "r"(a3), "r"(b0), "r"(b1));
}

// XOR-swizzled smem offset for 32B rows (BK=16), 16B chunks
__device__ __forceinline__ uint32_t sw32(int row, int chunk) {
    return (uint32_t)(row * 32 + 16 * (chunk ^ ((row >> 2) & 1)));
}

// ===================================================================
// Kernel 1: build split-fp16 P + invden
// ===================================================================
__global__ void __launch_bounds__(576) build_pv_kernel(const float* __restrict__ x)
{
    int b = blockIdx.y;
    int l = blockIdx.x;
    int li = l >> 6, lj = l & 63;
    int t = threadIdx.x;
    int c = t & 63;
    int g = t >> 6;
    int dh = g / 3, dw = g % 3;

    const size_t xb = (size_t)b * HFULL * WFULL * CCH;

    int fi = li - 1 + dh;
    int fj = lj - 1 + dw;
    float pv = 0.0f;
    if (fi >= 0 && fi < HLO && fj >= 0 && fj < WLO) {
        size_t base = xb + (size_t)(2 * fi) * (WFULL * CCH) + (size_t)(2 * fj) * CCH + c;
        pv = 0.25f * (x[base] + x[base + CCH] + x[base + WFULL * CCH] + x[base + WFULL * CCH + CCH]);
    }
    __half hi = __float2half(pv);
    __half lo = __float2half(pv - __half2float(hi));
    size_t rb = ((size_t)b * LQ + l) * KP;
    g_Phf[rb + t] = hi;
    g_Phf[rb + KC + t] = lo;

    // norm reduce: warp shuffles + tiny cross-warp
    float sq = pv * pv;
#pragma unroll
    for (int off = 16; off >= 1; off >>= 1)
        sq += __shfl_xor_sync(0xffffffffu, sq, off);
    __shared__ float ws[18];
    int warp = t >> 5, lane = t & 31;
    if (lane == 0) ws[warp] = sq;
    __syncthreads();
    if (t == 0) {
        float s = 0.0f;
#pragma unroll
        for (int w = 0; w < 18; w++) s += ws[w];
        g_invden[b * LQ + l] = 1.0f / fmaxf(sqrtf(s), 1e-4f);
    }
}

// ===================================================================
// Kernel 2: mask gate
// ===================================================================
__global__ void mm_kernel(const float* __restrict__ mask)
{
    int idx = blockIdx.x * blockDim.x + threadIdx.x;
    if (idx >= BATCH * LQ) return;
    int b = idx / LQ;
    int l = idx % LQ;
    int li = l >> 6, lj = l & 63;
    const size_t mb = (size_t)b * HFULL * WFULL;

    float sum9 = 0.0f;
    for (int dh = 0; dh < 3; dh++) {
        for (int dw = 0; dw < 3; dw++) {
            int fi = li - 1 + dh, fj = lj - 1 + dw;
            if (fi >= 0 && fi < HLO && fj >= 0 && fj < WLO) {
                size_t base = mb + (size_t)(2 * fi) * WFULL + (2 * fj);
                sum9 += 0.25f * (mask[base] + mask[base + 1] + mask[base + WFULL] + mask[base + WFULL + 1]);
            }
        }
    }
    float mean = sum9 / 9.0f;
    g_mm[idx] = (mean == 1.0f) ? 1.0f : 0.0f;
}

// ===================================================================
// Kernel 2b: deterministic compaction of active columns (pad to 64)
// ===================================================================
__global__ void __launch_bounds__(1024) compact_kernel()
{
    int b = blockIdx.x;
    int t = threadIdx.x;
    __shared__ int sc[1024];

    int base = t * 4;
    int loc[4];
    int cnt = 0;
#pragma unroll
    for (int i = 0; i < 4; i++) {
        loc[i] = (g_mm[b * LQ + base + i] != 0.0f) ? 1 : 0;
        cnt += loc[i];
    }
    sc[t] = cnt;
    __syncthreads();
    for (int off = 1; off < 1024; off <<= 1) {
        int v = (t >= off) ? sc[t - off] : 0;
        __syncthreads();
        sc[t] += v;
        __syncthreads();
    }
    int pos = sc[t] - cnt;
#pragma unroll
    for (int i = 0; i < 4; i++) {
        if (loc[i]) g_idx[b * LQ + (pos++)] = base + i;
    }
    if (t == 1023) {
        int total = sc[1023];
        int pad = (total + 63) & ~63;
        g_cnt[b * 2 + 0] = total;
        g_cnt[b * 2 + 1] = pad;
        for (int j = total; j < pad; j++) g_idx[b * LQ + j] = 0;
    }
}

// ===================================================================
// Kernel 2c: compacted-transposed fp16 V read straight from x
// ===================================================================
__global__ void __launch_bounds__(256) vcompT_kernel(const float* __restrict__ x)
{
    int b = blockIdx.y;
    int n = blockIdx.x;
    int g = n >> 6;
    int c = n & 63;
    int dh = g / 3, dw = g % 3;
    int cnt = g_cnt[b * 2 + 0];
    int pad = g_cnt[b * 2 + 1];
    const int* __restrict__ idxb = g_idx + b * LQ;
    const float* __restrict__ xb = x + (size_t)b * HFULL * WFULL * CCH;
    __half* __restrict__ Vn = g_VT + ((size_t)b * KC + n) * LQ;

    for (int j = threadIdx.x; j < pad; j += 256) {
        float v = 0.0f;
        if (j < cnt) {
            int l = __ldg(idxb + j);
            int xr = 2 * (l >> 6) + dh;
            int xc = 2 * (l & 63) + dw;
            if (xr < HFULL && xc < WFULL)
                v = __ldg(xb + (size_t)xr * (WFULL * CCH) + (size_t)xc * CCH + c);
        }
        Vn[j] = __float2half(v);
    }
}

// ===================================================================
// Kernel 3: score GEMM, fp16 2-combo: (Ahi + Alo) . Bhi
// A side exact (fp16 split), B side fp16-quantized (= hi half).
// 128x128 tile, 8 warps (2x4), warp 64x32, BK=16,
// 4-stage cp.async ring (2 ahead, wait<2>), 2 CTAs/SM.
// Block-triangle symmetric.
// ===================================================================
#define STILE 4096             // one operand tile: 128 rows x 32B
#define SBUF  (3 * STILE)      // Ahi + Alo + Bhi = 12KB per stage

__global__ void __launch_bounds__(256, 2) gemm_s_mma_kernel(float* __restrict__ out)
{
    if (blockIdx.x < blockIdx.y) return;

    __shared__ __align__(16) unsigned char smem_raw[4 * SBUF];  // 48KB

    int t = threadIdx.x;
    int lane = t & 31;
    int wid = t >> 5;
    int warp_m = wid >> 2;       // 0..1
    int warp_n = wid & 3;        // 0..3
    int b = blockIdx.z;
    int p0 = blockIdx.y * 128;
    int q0 = blockIdx.x * 128;

    uint32_t sbase = smem_u32(smem_raw);
    const char* Abase = (const char*)g_Phf + ((size_t)b * LQ + p0) * (KP * 2);
    const char* Bbase = (const char*)g_Phf + ((size_t)b * LQ + q0) * (KP * 2);

    float acc[4][4][4];
#pragma unroll
    for (int i = 0; i < 4; i++)
#pragma unroll
        for (int j = 0; j < 4; j++)
#pragma unroll
            for (int k = 0; k < 4; k++) acc[i][j][k] = 0.0f;

    const int NIT = 36;     // 576 / 16
    // stage 3 tiles for chunk kc: Ahi, Alo, Bhi
    auto stage = [&](int buf, int kc) {
        uint32_t sdst = sbase + buf * SBUF;
        size_t col = (size_t)kc * 32;
#pragma unroll
        for (int r = 0; r < 3; r++) {
            int id = r * 256 + t;          // 0..767
            int tile = id >> 8;            // 0=Ahi 1=Alo 2=Bhi
            int rid = id & 255;
            int row = rid >> 1, u = rid & 1;
            const char* src = (tile < 2 ? Abase : Bbase)
                            + (size_t)row * (KP * 2) + col
                            + ((tile == 1) ? 1152 : 0)
                            + u * 16;
            cp16(sdst + tile * STILE + sw32(row, u), src);
        }
    };

    int lr = lane & 7, sel = lane >> 3;
    auto compute = [&](int buf) {
        uint32_t sAhi = sbase + buf * SBUF;
        uint32_t sAlo = sAhi + STILE;
        uint32_t sBhi = sAhi + 2 * STILE;

        uint32_t ah[4][4], al[4][4];
#pragma unroll
        for (int mt = 0; mt < 4; mt++) {
            int row = warp_m * 64 + mt * 16 + lr + (sel & 1) * 8;
            int cc = sel >> 1;
            ldsm4(sAhi + sw32(row, cc), ah[mt][0], ah[mt][1], ah[mt][2], ah[mt][3]);
            ldsm4(sAlo + sw32(row, cc), al[mt][0], al[mt][1], al[mt][2], al[mt][3]);
        }
        uint32_t bh[2][4];
#pragma unroll
        for (int ntp = 0; ntp < 2; ntp++) {
            int row = warp_n * 32 + ntp * 16 + lr + (sel >> 1) * 8;
            int cc = sel & 1;
            ldsm4(sBhi + sw32(row, cc), bh[ntp][0], bh[ntp][1], bh[ntp][2], bh[ntp][3]);
        }
#pragma unroll
        for (int mt = 0; mt < 4; mt++)
#pragma unroll
            for (int nt = 0; nt < 4; nt++) {
                int g = nt >> 1, h = (nt & 1) * 2;
                mma16816h(acc[mt][nt][0], acc[mt][nt][1], acc[mt][nt][2], acc[mt][nt][3],
                          ah[mt][0], ah[mt][1], ah[mt][2], ah[mt][3], bh[g][h], bh[g][h + 1]);
                mma16816h(acc[mt][nt][0], acc[mt][nt][1], acc[mt][nt][2], acc[mt][nt][3],
                          al[mt][0], al[mt][1], al[mt][2], al[mt][3], bh[g][h], bh[g][h + 1]);
            }
    };

    stage(0, 0); cp_commit();
    stage(1, 1); cp_commit();
    for (int it = 0; it < NIT; it++) {
        if (it + 2 < NIT) {
            stage((it + 2) & 3, it + 2);
            cp_commit();
            cp_wait<2>();
        } else if (it + 1 < NIT) {
            cp_wait<1>();
        } else {
            cp_wait<0>();
        }
        __syncthreads();
        compute(it & 3);
    }

    // ---- epilogue: two 64-row phases through SMEM; write both halves ----
    const float* __restrict__ inv = g_invden + b * LQ;
    float* __restrict__ Cb = out + YSZ + (size_t)b * LQ * LQ;
    float* S = (float*)smem_raw;   // 64 x 132 floats = 33792 B <= 48KB

#pragma unroll
    for (int mhalf = 0; mhalf < 2; mhalf++) {
        __syncthreads();
        if (warp_m == mhalf) {
            int r0l = lane >> 2;
            int c0l = (lane & 3) * 2;
#pragma unroll
            for (int mt = 0; mt < 4; mt++)
#pragma unroll
                for (int nt = 0; nt < 4; nt++) {
                    int rr = mt * 16 + r0l;
                    int cc = warp_n * 32 + nt * 8 + c0l;
                    S[rr * 132 + cc]           = acc[mt][nt][0];
                    S[rr * 132 + cc + 1]       = acc[mt][nt][1];
                    S[(rr + 8) * 132 + cc]     = acc[mt][nt][2];
                    S[(rr + 8) * 132 + cc + 1] = acc[mt][nt][3];
                }
        }
        __syncthreads();
        {
            int r = t >> 2, cs = (t & 3) * 32;
            float* dst = Cb + (size_t)(p0 + mhalf * 64 + r) * LQ + q0 + cs;
            const float* sp = S + r * 132 + cs;
#pragma unroll 8
            for (int j = 0; j < 32; j++)
                dst[j] = sp[j] * __ldg(inv + q0 + cs + j);
        }
        {
            int c = t >> 1, rs = (t & 1) * 32;
            float* dst = Cb + (size_t)(q0 + c) * LQ + p0 + mhalf * 64 + rs;
#pragma unroll 8
            for (int i = 0; i < 32; i++)
                dst[i] = S[(rs + i) * 132 + c] * __ldg(inv + p0 + mhalf * 64 + rs + i);
        }
    }
}

// ===================================================================
// Kernel 4: fuse + stable softmax -> split-fp16 U.
// 4 p per block (consecutive ap => shared gather rows stay L1-hot).
// ===================================================================
__global__ void __launch_bounds__(256) fuse_softmax_kernel(const float* __restrict__ out)
{
    int b = blockIdx.y;
    int bx = blockIdx.x;
    int qj = bx & 63;
    int qi0 = (bx >> 6) << 2;

    const float* __restrict__ ab = out + YSZ + (size_t)b * LQ * LQ;
    const int* __restrict__ idxb = g_idx + b * LQ;

    int cnt = g_cnt[b * 2 + 0];
    int pad = g_cnt[b * 2 + 1];

    __shared__ float zbuf[LQ];
    __shared__ float red[256];

    int t = threadIdx.x;

    for (int sub = 0; sub < 4; sub++) {
        int qi = qi0 + sub;
        int p = (qi << 6) | qj;
        int ap = (qj << 6) | qi;
        __half* __restrict__ Uhp = g_Uhi + ((size_t)b * LQ + p) * LQ;
        __half* __restrict__ Ulp = g_Ulo + ((size_t)b * LQ + p) * LQ;

        float lmax = (cnt < LQ) ? 0.0f : -3.4e38f;

        for (int j = t; j < pad; j += 256) {
            float z = 0.0f;
            if (j < cnt) {
                int l = __ldg(idxb + j);
                int ki = l >> 6, kj = l & 63;
                int bp = (kj << 6) | ki;
                float acc = 0.0f;
#pragma unroll
                for (int d2 = -1; d2 <= 1; d2++) {
                    int aa = ap + d2;
                    int bb = bp + d2;
                    if ((unsigned)aa < LQ && (unsigned)bb < LQ) {
                        int u0 = ((aa & 63) << 6) | (aa >> 6);
                        int v0 = ((bb & 63) << 6) | (bb >> 6);
#pragma unroll
                        for (int d1 = -1; d1 <= 1; d1++) {
                            int uu = u0 + d1, vv = v0 + d1;
                            if ((unsigned)uu < LQ && (unsigned)vv < LQ)
                                acc += __ldg(ab + (size_t)uu * LQ + vv);
                        }
                    }
                }
                z = acc * 10.0f;
                lmax = fmaxf(lmax, z);
            }
            zbuf[j] = z;
        }

        red[t] = lmax;
        __syncthreads();
        for (int off = 128; off >= 1; off >>= 1) {
            if (t < off) red[t] = fmaxf(red[t], red[t + off]);
            __syncthreads();
        }
        float rmax = red[0];
        __syncthreads();

        float lsum = 0.0f;
        for (int j = t; j < pad; j += 256) {
            float e = 0.0f;
            if (j < cnt) {
                e = expf(zbuf[j] - rmax);
                lsum += e;
            }
            zbuf[j] = e;
        }
        red[t] = lsum;
        __syncthreads();
        for (int off = 128; off >= 1; off >>= 1) {
            if (t < off) red[t] += red[t + off];
            __syncthreads();
        }
        float den = red[0] + (float)(LQ - cnt) * expf(-rmax);
        float invs = 1.0f / den;
        __syncthreads();

        for (int j = t; j < pad; j += 256) {
            float val = zbuf[j] * invs;
            __half hi = __float2half(val);
            Uhp[j] = hi;
            Ulp[j] = __float2half(val - __half2float(hi));
        }
        __syncthreads();
    }
}

// ===================================================================
// Kernel 5: recon GEMM via fp16 mma.sync, 2-combo:
// Z = (Uhi + Ulo) @ fp16(V)^T. 128x96 tile, warp 64x24, BK=16,
// 4-stage ring, 2 CTAs/SM.
// ===================================================================
#define ZTA 4096   // U tile: 128 x 32B
#define ZTB 3072   // VT tile: 96 x 32B
#define ZBUF (2 * ZTA + ZTB)   // 11KB per stage

__global__ void __launch_bounds__(256, 2) gemm_z_mma_kernel()
{
    __shared__ __align__(16) unsigned char smem_raw[4 * ZBUF];  // 44KB

    int t = threadIdx.x;
    int lane = t & 31;
    int wid = t >> 5;
    int warp_m = wid >> 2;       // 0..1
    int warp_n = wid & 3;        // 0..3
    int b = blockIdx.z;
    int p0 = blockIdx.y * 128;
    int n0 = blockIdx.x * 96;

    int kmax = g_cnt[b * 2 + 1];            // 64-aligned
    int NIT = kmax >> 4;                     // BK=16 chunks

    uint32_t sbase = smem_u32(smem_raw);
    const char* Ah = (const char*)(g_Uhi + ((size_t)b * LQ + p0) * LQ);
    const char* Al = (const char*)(g_Ulo + ((size_t)b * LQ + p0) * LQ);
    const char* Bh = (const char*)(g_VT + ((size_t)b * KC + n0) * LQ);

    float acc[4][3][4];
#pragma unroll
    for (int i = 0; i < 4; i++)
#pragma unroll
        for (int j = 0; j < 3; j++)
#pragma unroll
            for (int k = 0; k < 4; k++) acc[i][j][k] = 0.0f;

    auto stage = [&](int buf, int kc) {
        uint32_t sdst = sbase + buf * ZBUF;
        size_t col = (size_t)kc * 32;
        for (int i = t; i < 704; i += 256) {
            if (i < 512) {
                const char* src = (i < 256) ? Ah : Al;
                uint32_t base = sdst + ((i < 256) ? 0 : ZTA);
                int rid = i & 255;
                int row = rid >> 1, u = rid & 1;
                cp16(base + sw32(row, u), src + (size_t)row * (LQ * 2) + col + u * 16);
            } else {
                int j = i - 512;                 // 0..191
                int row = j >> 1, u = j & 1;
                cp16(sdst + 2 * ZTA + sw32(row, u), Bh + (size_t)row * (LQ * 2) + col + u * 16);
            }
        }
    };

    int lr = lane & 7, sel = lane >> 3;
    int half2 = (lane >> 3) & 1;
    auto compute = [&](int buf) {
        uint32_t sAh = sbase + buf * ZBUF;
        uint32_t sAl = sAh + ZTA;
        uint32_t sBh = sAh + 2 * ZTA;

        uint32_t ah[4][4], al[4][4];
#pragma unroll
        for (int mt = 0; mt < 4; mt++) {
            int row = warp_m * 64 + mt * 16 + lr + (sel & 1) * 8;
            int cc = sel >> 1;
            ldsm4(sAh + sw32(row, cc), ah[mt][0], ah[mt][1], ah[mt][2], ah[mt][3]);
            ldsm4(sAl + sw32(row, cc), al[mt][0], al[mt][1], al[mt][2], al[mt][3]);
        }
        uint32_t bh[6];
        {
            int row = warp_n * 24 + lr + (sel >> 1) * 8;
            int cc = sel & 1;
            ldsm4(sBh + sw32(row, cc), bh[0], bh[1], bh[2], bh[3]);
        }
        {
            int row = warp_n * 24 + 16 + lr;
            int cc = half2;
            ldsm2(sBh + sw32(row, cc), bh[4], bh[5]);
        }
#pragma unroll
        for (int mt = 0; mt < 4; mt++)
#pragma unroll
            for (int nt = 0; nt < 3; nt++) {
                mma16816h(acc[mt][nt][0], acc[mt][nt][1], acc[mt][nt][2], acc[mt][nt][3],
                          ah[mt][0], ah[mt][1], ah[mt][2], ah[mt][3], bh[nt * 2], bh[nt * 2 + 1]);
                mma16816h(acc[mt][nt][0], acc[mt][nt][1], acc[mt][nt][2], acc[mt][nt][3],
                          al[mt][0], al[mt][1], al[mt][2], al[mt][3], bh[nt * 2], bh[nt * 2 + 1]);
            }
    };

    stage(0, 0); cp_commit();
    stage(1, 1); cp_commit();
    for (int it = 0; it < NIT; it++) {
        if (it + 2 < NIT) {
            stage((it + 2) & 3, it + 2);
            cp_commit();
            cp_wait<2>();
        } else if (it + 1 < NIT) {
            cp_wait<1>();
        } else {
            cp_wait<0>();
        }
        __syncthreads();
        compute(it & 3);
    }

    // epilogue: direct float2 stores to g_Z
    float* __restrict__ Zb = g_Z + (size_t)b * LQ * KC;
    int r0l = lane >> 2;
    int c0l = (lane & 3) * 2;
#pragma unroll
    for (int mt = 0; mt < 4; mt++)
#pragma unroll
        for (int nt = 0; nt < 3; nt++) {
            int row = p0 + warp_m * 64 + mt * 16 + r0l;
            int col = n0 + warp_n * 24 + nt * 8 + c0l;
            *(float2*)(Zb + (size_t)row * KC + col) =
                make_float2(acc[mt][nt][0], acc[mt][nt][1]);
            *(float2*)(Zb + (size_t)(row + 8) * KC + col) =
                make_float2(acc[mt][nt][2], acc[mt][nt][3]);
        }
}

// ===================================================================
// Kernel 6: overlap-add (transposed conv gather), float4 per thread
// ===================================================================
__global__ void recon_kernel(float* __restrict__ out)
{
    int idx = blockIdx.x * blockDim.x + threadIdx.x;  // over YSZ/4
    if (idx >= (int)(YSZ / 4)) return;
    int c4 = (idx & 15) * 4;       // channel base
    int tmp = idx >> 4;
    int J = tmp & 127; tmp >>= 7;
    int I = tmp & 127;
    int b = tmp >> 7;

    int ri[2], rdh[2], rn = 0;
    if (I & 1) { ri[0] = (I - 1) >> 1; rdh[0] = 1; rn = 1; }
    else {
        ri[rn] = I >> 1; rdh[rn] = 0; rn++;
        if (I >= 2) { ri[rn] = (I >> 1) - 1; rdh[rn] = 2; rn++; }
    }
    int cj[2], cdw[2], cn = 0;
    if (J & 1) { cj[0] = (J - 1) >> 1; cdw[0] = 1; cn = 1; }
    else {
        cj[cn] = J >> 1; cdw[cn] = 0; cn++;
        if (J >= 2) { cj[cn] = (J >> 1) - 1; cdw[cn] = 2; cn++; }
    }

    const float* __restrict__ Zb = g_Z + (size_t)b * LQ * KC;
    float4 acc = make_float4(0.f, 0.f, 0.f, 0.f);
    for (int a = 0; a < rn; a++) {
        for (int bb = 0; bb < cn; bb++) {
            int l = ri[a] * 64 + cj[bb];
            int n = (rdh[a] * 3 + cdw[bb]) * 64 + c4;
            float4 v = *(const float4*)(Zb + (size_t)l * KC + n);
            acc.x += v.x; acc.y += v.y; acc.z += v.z; acc.w += v.w;
        }
    }
    acc.x *= 0.25f; acc.y *= 0.25f; acc.z *= 0.25f; acc.w *= 0.25f;
    size_t o = (((size_t)b * HFULL + I) * WFULL + J) * CCH + c4;
    *(float4*)(out + o) = acc;
}

// ===================================================================
extern "C" void kernel_launch(void* const* d_in, const int* in_sizes, int n_in,
                              void* d_out, int out_size)
{
    const float* x    = (const float*)d_in[0];
    const float* mask = (const float*)d_in[1];
    float* out = (float*)d_out;
    (void)in_sizes; (void)n_in; (void)out_size;

    build_pv_kernel<<<dim3(LQ, BATCH), 576>>>(x);
    mm_kernel<<<(BATCH * LQ + 255) / 256, 256>>>(mask);
    compact_kernel<<<BATCH, 1024>>>();
    vcompT_kernel<<<dim3(KC, BATCH), 256>>>(x);
    gemm_s_mma_kernel<<<dim3(32, 32, BATCH), 256>>>(out);
    fuse_softmax_kernel<<<dim3(1024, BATCH), 256>>>(out);
    gemm_z_mma_kernel<<<dim3(6, 32, BATCH), 256>>>();
    recon_kernel<<<(int)(YSZ / 4 + 255) / 256, 256>>>(out);
}